// round 13
// baseline (speedup 1.0000x reference)
#include <cuda_runtime.h>
#include <cuda_bf16.h>
#include <math.h>
#include <stdint.h>

#define NLAYER 8
#define DMODEL 512
#define DINNER 1024
#define DSTATE 16
#define DCONV  4
#define DTRANK 32
#define BATCH  8
#define SEQ    800
#define MROWS  (BATCH*SEQ)   // 6400

// ---------------- scratch (static device globals) ------------------------------
__device__ float g_pin [MROWS*1024];
__device__ float g_xt  [MROWS*DMODEL];
__device__ float g_xz  [MROWS*2*DINNER];
__device__ float g_xcf [MROWS*DINNER];
__device__ float g_xcb [MROWS*DINNER];
__device__ float g_prjf[MROWS*64];
__device__ float g_prjb[MROWS*64];
__device__ float g_dtf [MROWS*DINNER];
__device__ float g_dtb [MROWS*DINNER];
__device__ float g_yf  [MROWS*DINNER];
__device__ float g_yb  [MROWS*DINNER];
__device__ float g_t512[MROWS*DMODEL];
__device__ float g_mid [MROWS*DINNER];
// bf16 split operands (16B aligned for cp.async)
__device__ __align__(16) __nv_bfloat16 g_ap[(size_t)MROWS*3072];
__device__ __align__(16) __nv_bfloat16 g_bp[(size_t)2048*1536];

#define EPI_NONE     0
#define EPI_BIAS     1
#define EPI_SOFTPLUS 2
#define EPI_GELU     3

__device__ __forceinline__ float silu_f(float x) {
    return x * (1.0f / (1.0f + __expf(-x)));
}

__device__ __forceinline__ uint32_t smem_u32(const void* p) {
    uint32_t a;
    asm("{ .reg .u64 t; cvta.to.shared.u64 t, %1; cvt.u32.u64 %0, t; }"
        : "=r"(a) : "l"(p));
    return a;
}

// ---------------- baseline-PTX async copy + ldmatrix + mma ---------------------
#define CP_ASYNC16(dst, src) \
    asm volatile("cp.async.cg.shared.global [%0], [%1], 16;" \
                 :: "r"(dst), "l"(src))
#define CP_COMMIT() asm volatile("cp.async.commit_group;" ::: "memory")
#define CP_WAIT(n)  asm volatile("cp.async.wait_group %0;" :: "n"(n) : "memory")

#define LDMATRIX_X4(r0, r1, r2, r3, addr) \
    asm volatile("ldmatrix.sync.aligned.m8n8.x4.shared.b16 {%0,%1,%2,%3}, [%4];" \
                 : "=r"(r0), "=r"(r1), "=r"(r2), "=r"(r3) : "r"(addr))

#define MMA16816(c, a, b0v, b1v) \
    asm volatile("mma.sync.aligned.m16n8k16.row.col.f32.bf16.bf16.f32 " \
                 "{%0,%1,%2,%3}, {%4,%5,%6,%7}, {%8,%9}, {%0,%1,%2,%3};" \
                 : "+f"((c)[0]), "+f"((c)[1]), "+f"((c)[2]), "+f"((c)[3]) \
                 : "r"((a)[0]), "r"((a)[1]), "r"((a)[2]), "r"((a)[3]), \
                   "r"(b0v), "r"(b1v))

// ---------------- split-precision conversion kernels ---------------------------
// A' = [hi | hi | lo] over K, zero-padded to Kp (A2 optionally added first)
__global__ void asplit_k(const float* __restrict__ A, const float* __restrict__ A2,
                         int lda, int K, int Kp, int M, __nv_bfloat16* __restrict__ Ap)
{
    int idx = blockIdx.x * 256 + threadIdx.x;
    if (idx >= M * Kp) return;
    int c = idx % Kp, r = idx / Kp;
    int seg = -1, k = 0;
    if (c < K)          { k = c;       seg = 0; }
    else if (c < 2*K)   { k = c - K;   seg = 0; }
    else if (c < 3*K)   { k = c - 2*K; seg = 1; }
    __nv_bfloat16 o = __float2bfloat16(0.0f);
    if (seg >= 0) {
        float v = A[(size_t)r*lda + k];
        if (A2) v += A2[(size_t)r*lda + k];
        __nv_bfloat16 hi = __float2bfloat16(v);
        o = (seg == 0) ? hi : __float2bfloat16(v - __bfloat162float(hi));
    }
    Ap[idx] = o;
}

// B' (transposed): W[K x N] -> Bp[N x Kp], segments over K: [hi | lo | hi], pad 0
__global__ void bsplit_k(const float* __restrict__ W, int K, int N, int Kp,
                         __nv_bfloat16* __restrict__ Bp)
{
    int idx = blockIdx.x * 256 + threadIdx.x;
    if (idx >= N * Kp) return;
    int c = idx % Kp, n = idx / Kp;
    int seg = -1, k = 0;
    if (c < K)          { k = c;       seg = 0; }
    else if (c < 2*K)   { k = c - K;   seg = 1; }
    else if (c < 3*K)   { k = c - 2*K; seg = 0; }
    __nv_bfloat16 o = __float2bfloat16(0.0f);
    if (seg >= 0) {
        float v = W[(size_t)k*N + n];
        __nv_bfloat16 hi = __float2bfloat16(v);
        o = (seg == 1) ? __float2bfloat16(v - __bfloat162float(hi)) : hi;
    }
    Bp[idx] = o;
}

// ---------------- bf16 mma.sync GEMM -------------------------------------------
// C[M,N] (fp32) = Ap[M x Kp] @ Bp[N x Kp]^T, epilogue fused.
// Block tile BM x BN, 256 threads = 8 warps (2 M x 4 N). K-chunks of 32 bf16,
// cp.async 2-stage double buffer. Smem rows padded to 80B (ldmatrix conflict-free).
template<int BM, int BN, int EPI>
__global__ __launch_bounds__(256)
void mgemm_k(const __nv_bfloat16* __restrict__ Ap, int lda,
             const __nv_bfloat16* __restrict__ Bp, int ldb,
             const float* __restrict__ bias,
             float* __restrict__ C, int ldc, int Kp)
{
    constexpr int MT  = BM/32;        // m16 tiles per warp
    constexpr int NTN = BN/32;        // n8 tiles per warp
    constexpr int CH  = (BM + BN)*80; // bytes per stage

    extern __shared__ char smem[];
    const uint32_t sbase = smem_u32(smem);
    const int tid  = threadIdx.x;
    const int lane = tid & 31, wid = tid >> 5;
    const int wm = wid & 1, wn = wid >> 1;
    const int m0 = blockIdx.y * BM;
    const int n0 = blockIdx.x * BN;

    float acc[MT][NTN][4];
#pragma unroll
    for (int i = 0; i < MT; i++)
#pragma unroll
        for (int j = 0; j < NTN; j++)
#pragma unroll
            for (int q = 0; q < 4; q++) acc[i][j][q] = 0.0f;

    const int NC = Kp >> 5;   // chunks of 32 bf16 (64B)

    auto stage = [&](int buf, int ck) {
        uint32_t sA = sbase + buf*CH;
        uint32_t sB = sA + BM*80;
        const __nv_bfloat16* Ag = Ap + (size_t)m0*lda + ck*32;
#pragma unroll
        for (int i = 0; i < BM/64; i++) {
            int q = tid + i*256;
            int r = q >> 2, sg = q & 3;
            CP_ASYNC16(sA + r*80 + sg*16, Ag + (size_t)r*lda + sg*8);
        }
        const __nv_bfloat16* Bg = Bp + (size_t)n0*ldb + ck*32;
#pragma unroll
        for (int i = 0; i < BN/64; i++) {
            int q = tid + i*256;
            int r = q >> 2, sg = q & 3;
            CP_ASYNC16(sB + r*80 + sg*16, Bg + (size_t)r*ldb + sg*8);
        }
    };

    // ldmatrix lane-address templates (byte offsets within a stage)
    const uint32_t a_off = (uint32_t)((wm*(BM/2) + (lane & 15)) * 80 + (lane >> 4)*16);
    const uint32_t b_off = (uint32_t)(BM*80 +
        (wn*(BN/4) + (lane & 7) + ((lane >> 4) << 3)) * 80 + (((lane >> 3) & 1)*16));

    auto compute = [&](int buf) {
        const uint32_t s0 = sbase + buf*CH;
#pragma unroll
        for (int ks = 0; ks < 2; ks++) {
            uint32_t af[MT][4];
#pragma unroll
            for (int mt = 0; mt < MT; mt++)
                LDMATRIX_X4(af[mt][0], af[mt][1], af[mt][2], af[mt][3],
                            s0 + a_off + (uint32_t)(mt*16*80 + ks*32));
#pragma unroll
            for (int nb = 0; nb < NTN/2; nb++) {
                uint32_t bf[4];
                LDMATRIX_X4(bf[0], bf[1], bf[2], bf[3],
                            s0 + b_off + (uint32_t)(nb*16*80 + ks*32));
#pragma unroll
                for (int mt = 0; mt < MT; mt++) {
                    MMA16816(acc[mt][2*nb+0], af[mt], bf[0], bf[1]);
                    MMA16816(acc[mt][2*nb+1], af[mt], bf[2], bf[3]);
                }
            }
        }
    };

    stage(0, 0); CP_COMMIT();
    int buf = 0;
    for (int ck = 0; ck < NC; ck++) {
        if (ck + 1 < NC) {
            stage(buf ^ 1, ck + 1); CP_COMMIT();
            CP_WAIT(1);
        } else {
            CP_WAIT(0);
        }
        __syncthreads();
        compute(buf);
        __syncthreads();
        buf ^= 1;
    }

    // epilogue: fragment layout c = {C[m][n], C[m][n+1], C[m+8][n], C[m+8][n+1]}
    const int gid = lane >> 2, tig = lane & 3;
#pragma unroll
    for (int mt = 0; mt < MT; mt++) {
#pragma unroll
        for (int nt = 0; nt < NTN; nt++) {
            int m = m0 + wm*(BM/2) + mt*16 + gid;
            int n = n0 + wn*(BN/4) + nt*8 + tig*2;
            float v[4] = {acc[mt][nt][0], acc[mt][nt][1],
                          acc[mt][nt][2], acc[mt][nt][3]};
#pragma unroll
            for (int q = 0; q < 4; q++) {
                float w = v[q];
                if (EPI == EPI_BIAS || EPI == EPI_SOFTPLUS || EPI == EPI_GELU)
                    w += bias[n + (q & 1)];
                if (EPI == EPI_SOFTPLUS)
                    w = (w > 0.0f) ? (w + log1pf(__expf(-w))) : log1pf(__expf(w));
                if (EPI == EPI_GELU)
                    w = 0.5f * w * (1.0f + erff(w * 0.70710678118654752f));
                v[q] = w;
            }
            *reinterpret_cast<float2*>(C + (size_t)m*ldc + n)       = make_float2(v[0], v[1]);
            *reinterpret_cast<float2*>(C + (size_t)(m+8)*ldc + n)   = make_float2(v[2], v[3]);
        }
    }
}

static inline int round64(int x) { return (x + 63) & ~63; }

template<int BM, int BN, int EPI>
static void rb_gemm(const float* A, const float* A2, int lda, int K,
                    const float* W, int N, const float* bias,
                    float* C, __nv_bfloat16* ap, __nv_bfloat16* bp)
{
    const int Kp = round64(3*K);
    asplit_k<<<(MROWS*Kp + 255)/256, 256>>>(A, A2, lda, K, Kp, MROWS, ap);
    bsplit_k<<<(N*Kp + 255)/256, 256>>>(W, K, N, Kp, bp);
    dim3 grid(N/BN, MROWS/BM);
    mgemm_k<BM, BN, EPI><<<grid, 256, 2*(BM+BN)*80>>>(ap, Kp, bp, Kp, bias, C, N, Kp);
}

// ---------------- patch gather -------------------------------------------------
__global__ void gather_k(const float* __restrict__ x, float* __restrict__ pin)
{
    int idx = blockIdx.x * blockDim.x + threadIdx.x;
    if (idx >= MROWS*1024) return;
    int k   = idx & 1023;
    int row = idx >> 10;
    int b = row / SEQ, t = row % SEQ;
    int f = t / 100, rem = t % 100;
    int hh = rem / 10, ww = rem % 10;
    int p1 = k >> 6;
    int r2 = k & 63;
    int p2 = r2 >> 2;
    int pf = r2 & 3;
    size_t src = (((size_t)b*32 + (f*4 + pf))*160 + (hh*16 + p1))*160 + (ww*16 + p2);
    pin[idx] = x[src];
}

// ---------------- depthwise causal conv (fwd + reversed) + SiLU ----------------
__global__ void conv_k(const float* __restrict__ xz,
                       const float* __restrict__ wf, const float* __restrict__ bf,
                       const float* __restrict__ wb, const float* __restrict__ bb,
                       float* __restrict__ xcf, float* __restrict__ xcb)
{
    int idx = blockIdx.x * blockDim.x + threadIdx.x;
    if (idx >= MROWS*DINNER) return;
    int d   = idx & (DINNER-1);
    int row = idx >> 10;
    int b = row / SEQ, t = row % SEQ;
    const float* base = xz + (size_t)b*SEQ*2048 + d;

    float w0 = wf[d*4+0], w1 = wf[d*4+1], w2 = wf[d*4+2], w3 = wf[d*4+3];
    float acc = bf[d];
    acc = fmaf(w3, base[(size_t)t*2048], acc);
    if (t >= 1) acc = fmaf(w2, base[(size_t)(t-1)*2048], acc);
    if (t >= 2) acc = fmaf(w1, base[(size_t)(t-2)*2048], acc);
    if (t >= 3) acc = fmaf(w0, base[(size_t)(t-3)*2048], acc);
    xcf[(size_t)row*DINNER + d] = silu_f(acc);

    float v0 = wb[d*4+0], v1 = wb[d*4+1], v2 = wb[d*4+2], v3 = wb[d*4+3];
    float accb = bb[d];
    accb = fmaf(v3, base[(size_t)(SEQ-1-t)*2048], accb);
    if (t >= 1) accb = fmaf(v2, base[(size_t)(SEQ-t)*2048], accb);
    if (t >= 2) accb = fmaf(v1, base[(size_t)(SEQ+1-t)*2048], accb);
    if (t >= 3) accb = fmaf(v0, base[(size_t)(SEQ+2-t)*2048], accb);
    xcb[(size_t)row*DINNER + d] = silu_f(accb);
}

// ---------------- selective-scan (both directions) -----------------------------
__global__ __launch_bounds__(128)
void scan_k(const float* __restrict__ dtf, const float* __restrict__ dtb,
            const float* __restrict__ uf,  const float* __restrict__ ub,
            const float* __restrict__ pf,  const float* __restrict__ pb,
            const float* __restrict__ Af,  const float* __restrict__ Ab,
            const float* __restrict__ Df,  const float* __restrict__ Db,
            const float* __restrict__ xz,
            float* __restrict__ yf, float* __restrict__ yb)
{
    const int d   = blockIdx.x * 128 + threadIdx.x;
    const int b   = blockIdx.y;
    const int dir = blockIdx.z;

    const float* dtp = dir ? dtb : dtf;
    const float* up  = dir ? ub  : uf;
    const float* pp  = dir ? pb  : pf;
    const float* Ap  = dir ? Ab  : Af;
    const float* Dp  = dir ? Db  : Df;
    float*       yp  = dir ? yb  : yf;

    float A[DSTATE];
#pragma unroll
    for (int n = 0; n < DSTATE; n++) A[n] = -expf(Ap[(size_t)d*DSTATE + n]);
    const float Dv = Dp[d];

    bool fast = true;
#pragma unroll
    for (int n = 1; n < DSTATE; n++) {
        float ex = A[0] * (float)(n+1);
        fast = fast && (fabsf(A[n] - ex) <= 1e-4f * fabsf(ex) + 1e-6f);
    }

    float h[DSTATE];
#pragma unroll
    for (int n = 0; n < DSTATE; n++) h[n] = 0.0f;

    int row = b*SEQ;
    float dt_c = dtp[(size_t)row*DINNER + d];
    float u_c  = up [(size_t)row*DINNER + d];
    const float4* bc = reinterpret_cast<const float4*>(pp + (size_t)row*64 + 32);
    float4 Bq[4] = {bc[0], bc[1], bc[2], bc[3]};
    float4 Cq[4] = {bc[4], bc[5], bc[6], bc[7]};
    int orow0 = dir ? (b*SEQ + SEQ-1) : row;
    float z_c = xz[(size_t)orow0*2048 + DINNER + d];

    for (int t = 0; t < SEQ; t++) {
        const float dt = dt_c, u = u_c, zv = z_c;
        float Bv[16] = {Bq[0].x,Bq[0].y,Bq[0].z,Bq[0].w, Bq[1].x,Bq[1].y,Bq[1].z,Bq[1].w,
                        Bq[2].x,Bq[2].y,Bq[2].z,Bq[2].w, Bq[3].x,Bq[3].y,Bq[3].z,Bq[3].w};
        float Cv[16] = {Cq[0].x,Cq[0].y,Cq[0].z,Cq[0].w, Cq[1].x,Cq[1].y,Cq[1].z,Cq[1].w,
                        Cq[2].x,Cq[2].y,Cq[2].z,Cq[2].w, Cq[3].x,Cq[3].y,Cq[3].z,Cq[3].w};
        const int orow = dir ? (b*SEQ + (SEQ-1-t)) : (b*SEQ + t);

        if (t + 1 < SEQ) {
            const int nrow = b*SEQ + t + 1;
            dt_c = dtp[(size_t)nrow*DINNER + d];
            u_c  = up [(size_t)nrow*DINNER + d];
            const float4* nbc = reinterpret_cast<const float4*>(pp + (size_t)nrow*64 + 32);
            Bq[0]=nbc[0]; Bq[1]=nbc[1]; Bq[2]=nbc[2]; Bq[3]=nbc[3];
            Cq[0]=nbc[4]; Cq[1]=nbc[5]; Cq[2]=nbc[6]; Cq[3]=nbc[7];
            const int norow = dir ? (b*SEQ + (SEQ-2-t)) : nrow;
            z_c = xz[(size_t)norow*2048 + DINNER + d];
        }

        float e[16];
        if (fast) {
            float r  = __expf(dt * A[0]);
            float r2 = r*r, r4 = r2*r2, r8 = r4*r4;
            e[0]=r;       e[1]=r2;      e[2]=r2*r;     e[3]=r4;
            e[4]=r4*r;    e[5]=r4*r2;   e[6]=r4*e[2];  e[7]=r8;
            e[8]=r8*r;    e[9]=r8*r2;   e[10]=r8*e[2]; e[11]=r8*r4;
            e[12]=r8*e[4];e[13]=r8*e[5];e[14]=r8*e[6]; e[15]=r8*r8;
        } else {
#pragma unroll
            for (int n = 0; n < 16; n++) e[n] = __expf(dt * A[n]);
        }

        const float du = dt * u;
        float a0=0.f, a1=0.f, a2=0.f, a3=0.f;
#pragma unroll
        for (int n = 0; n < 16; n += 4) {
            h[n+0] = fmaf(e[n+0], h[n+0], du * Bv[n+0]);
            h[n+1] = fmaf(e[n+1], h[n+1], du * Bv[n+1]);
            h[n+2] = fmaf(e[n+2], h[n+2], du * Bv[n+2]);
            h[n+3] = fmaf(e[n+3], h[n+3], du * Bv[n+3]);
            a0 = fmaf(h[n+0], Cv[n+0], a0);
            a1 = fmaf(h[n+1], Cv[n+1], a1);
            a2 = fmaf(h[n+2], Cv[n+2], a2);
            a3 = fmaf(h[n+3], Cv[n+3], a3);
        }
        float y = (a0+a1) + (a2+a3) + u * Dv;
        yp[(size_t)orow*DINNER + d] = y * silu_f(zv);
    }
}

// ---------------- LayerNorm + residual -----------------------------------------
__global__ __launch_bounds__(256)
void ln_res_k(const float* __restrict__ y, const float* __restrict__ g,
              const float* __restrict__ be, float* __restrict__ xt,
              float* __restrict__ outp)
{
    const int row = blockIdx.x;
    const int tid = threadIdx.x;
    const float v0 = y[(size_t)row*DMODEL + tid];
    const float v1 = y[(size_t)row*DMODEL + 256 + tid];
    float s  = v0 + v1;
    float ss = v0*v0 + v1*v1;
#pragma unroll
    for (int off = 16; off > 0; off >>= 1) {
        s  += __shfl_xor_sync(0xffffffffu, s,  off);
        ss += __shfl_xor_sync(0xffffffffu, ss, off);
    }
    __shared__ float sh[2][8];
    const int wid = tid >> 5, lane = tid & 31;
    if (lane == 0) { sh[0][wid] = s; sh[1][wid] = ss; }
    __syncthreads();
    float ts = 0.f, tss = 0.f;
#pragma unroll
    for (int i = 0; i < 8; i++) { ts += sh[0][i]; tss += sh[1][i]; }
    const float mean = ts * (1.0f/DMODEL);
    const float var  = tss * (1.0f/DMODEL) - mean*mean;
    const float rstd = rsqrtf(var + 1e-5f);

    float o0 = (v0 - mean)*rstd*g[tid]     + be[tid]     + xt[(size_t)row*DMODEL + tid];
    float o1 = (v1 - mean)*rstd*g[256+tid] + be[256+tid] + xt[(size_t)row*DMODEL + 256 + tid];
    xt[(size_t)row*DMODEL + tid]       = o0;
    xt[(size_t)row*DMODEL + 256 + tid] = o1;
    if (outp) {
        outp[(size_t)row*DMODEL + tid]       = o0;
        outp[(size_t)row*DMODEL + 256 + tid] = o1;
    }
}

// ---------------- host orchestration -------------------------------------------
extern "C" void kernel_launch(void* const* d_in, const int* in_sizes, int n_in,
                              void* d_out, int out_size)
{
    (void)in_sizes; (void)n_in; (void)out_size;
    const float* x        = (const float*)d_in[0];
    const float* patch_w  = (const float*)d_in[1];
    const float* patch_b  = (const float*)d_in[2];
    const float* in_proj  = (const float*)d_in[3];
    const float* conv_w   = (const float*)d_in[4];
    const float* conv_b   = (const float*)d_in[5];
    const float* xproj_w  = (const float*)d_in[6];
    const float* dt_w     = (const float*)d_in[7];
    const float* dt_bias  = (const float*)d_in[8];
    const float* A_log    = (const float*)d_in[9];
    const float* D_skip   = (const float*)d_in[10];
    const float* conv_wb  = (const float*)d_in[11];
    const float* conv_bb  = (const float*)d_in[12];
    const float* xproj_wb = (const float*)d_in[13];
    const float* dt_wb    = (const float*)d_in[14];
    const float* dt_biasb = (const float*)d_in[15];
    const float* A_logb   = (const float*)d_in[16];
    const float* D_skipb  = (const float*)d_in[17];
    const float* out_proj = (const float*)d_in[18];
    const float* ln1_g    = (const float*)d_in[19];
    const float* ln1_b    = (const float*)d_in[20];
    const float* fc1_w    = (const float*)d_in[21];
    const float* fc1_b    = (const float*)d_in[22];
    const float* fc2_w    = (const float*)d_in[23];
    const float* fc2_b    = (const float*)d_in[24];
    const float* ln2_g    = (const float*)d_in[25];
    const float* ln2_b    = (const float*)d_in[26];
    float* out = (float*)d_out;

    float *pin, *xt, *xz, *xcf, *xcb, *prjf, *prjb, *dtf, *dtb, *yf, *yb, *t512, *mid;
    __nv_bfloat16 *ap, *bp;
    cudaGetSymbolAddress((void**)&pin,  g_pin);
    cudaGetSymbolAddress((void**)&xt,   g_xt);
    cudaGetSymbolAddress((void**)&xz,   g_xz);
    cudaGetSymbolAddress((void**)&xcf,  g_xcf);
    cudaGetSymbolAddress((void**)&xcb,  g_xcb);
    cudaGetSymbolAddress((void**)&prjf, g_prjf);
    cudaGetSymbolAddress((void**)&prjb, g_prjb);
    cudaGetSymbolAddress((void**)&dtf,  g_dtf);
    cudaGetSymbolAddress((void**)&dtb,  g_dtb);
    cudaGetSymbolAddress((void**)&yf,   g_yf);
    cudaGetSymbolAddress((void**)&yb,   g_yb);
    cudaGetSymbolAddress((void**)&t512, g_t512);
    cudaGetSymbolAddress((void**)&mid,  g_mid);
    cudaGetSymbolAddress((void**)&ap,   g_ap);
    cudaGetSymbolAddress((void**)&bp,   g_bp);

    // patch embed: pin[6400x1024] @ patch_w[1024x512] + patch_b
    gather_k<<<(MROWS*1024 + 255)/256, 256>>>(x, pin);
    rb_gemm<128, 128, EPI_BIAS>(pin, nullptr, 1024, 1024, patch_w, 512, patch_b,
                                xt, ap, bp);

    for (int l = 0; l < NLAYER; l++) {
        // in_proj: xz[6400x2048] = xt @ W[512x2048]
        rb_gemm<128, 128, EPI_NONE>(xt, nullptr, 512, 512,
                                    in_proj + (size_t)l*512*2048, 2048, nullptr,
                                    xz, ap, bp);

        conv_k<<<(MROWS*DINNER + 255)/256, 256>>>(
            xz,
            conv_w  + (size_t)l*DINNER*DCONV, conv_b  + (size_t)l*DINNER,
            conv_wb + (size_t)l*DINNER*DCONV, conv_bb + (size_t)l*DINNER,
            xcf, xcb);

        // x-proj (N=64) — small N: 64x64 tiles for 100-CTA grids
        rb_gemm<64, 64, EPI_NONE>(xcf, nullptr, DINNER, DINNER,
                                  xproj_w + (size_t)l*DINNER*64, 64, nullptr,
                                  prjf, ap, bp);
        rb_gemm<64, 64, EPI_NONE>(xcb, nullptr, DINNER, DINNER,
                                  xproj_wb + (size_t)l*DINNER*64, 64, nullptr,
                                  prjb, ap, bp);

        // dt = softplus(prj[:, :32] @ dt_w[32x1024] + bias)
        rb_gemm<128, 128, EPI_SOFTPLUS>(prjf, nullptr, 64, DTRANK,
                                        dt_w + (size_t)l*DTRANK*DINNER, DINNER,
                                        dt_bias + (size_t)l*DINNER, dtf, ap, bp);
        rb_gemm<128, 128, EPI_SOFTPLUS>(prjb, nullptr, 64, DTRANK,
                                        dt_wb + (size_t)l*DTRANK*DINNER, DINNER,
                                        dt_biasb + (size_t)l*DINNER, dtb, ap, bp);

        scan_k<<<dim3(DINNER/128, BATCH, 2), 128>>>(
            dtf, dtb, xcf, xcb, prjf, prjb,
            A_log  + (size_t)l*DINNER*DSTATE, A_logb + (size_t)l*DINNER*DSTATE,
            D_skip + (size_t)l*DINNER,        D_skipb + (size_t)l*DINNER,
            xz, yf, yb);

        // out_proj on (yf + yb) — sum fused into asplit
        rb_gemm<128, 128, EPI_NONE>(yf, yb, DINNER, DINNER,
                                    out_proj + (size_t)l*DINNER*DMODEL, DMODEL, nullptr,
                                    t512, ap, bp);

        ln_res_k<<<MROWS, 256>>>(t512, ln1_g + (size_t)l*DMODEL,
                                 ln1_b + (size_t)l*DMODEL, xt, nullptr);

        rb_gemm<128, 128, EPI_GELU>(xt, nullptr, DMODEL, DMODEL,
                                    fc1_w + (size_t)l*DMODEL*1024, 1024,
                                    fc1_b + (size_t)l*1024, mid, ap, bp);
        rb_gemm<128, 128, EPI_BIAS>(mid, nullptr, 1024, 1024,
                                    fc2_w + (size_t)l*1024*DMODEL, DMODEL,
                                    fc2_b + (size_t)l*DMODEL, t512, ap, bp);

        ln_res_k<<<MROWS, 256>>>(t512, ln2_g + (size_t)l*DMODEL,
                                 ln2_b + (size_t)l*DMODEL, xt,
                                 out + (size_t)l*MROWS*DMODEL);
    }
}

// round 14
// speedup vs baseline: 1.5051x; 1.5051x over previous
#include <cuda_runtime.h>
#include <cuda_bf16.h>
#include <math.h>
#include <stdint.h>

#define NLAYER 8
#define DMODEL 512
#define DINNER 1024
#define DSTATE 16
#define DCONV  4
#define DTRANK 32
#define BATCH  8
#define SEQ    800
#define MROWS  (BATCH*SEQ)   // 6400

// ---------------- scratch (static device globals) ------------------------------
__device__ float g_pin [MROWS*1024];
__device__ float g_xt  [MROWS*DMODEL];
__device__ float g_xz  [MROWS*2*DINNER];
__device__ float g_xc  [2*MROWS*DINNER];   // fwd | bwd conv outputs
__device__ float g_prj [2*MROWS*64];       // fwd | bwd xproj outputs
__device__ float g_dt  [2*MROWS*DINNER];   // fwd | bwd dt
__device__ float g_yf  [MROWS*DINNER];
__device__ float g_yb  [MROWS*DINNER];
__device__ float g_t512[MROWS*DMODEL];
__device__ float g_mid [MROWS*DINNER];
// bf16 split operands (16B aligned for cp.async), 2 batches
__device__ __align__(16) __nv_bfloat16 g_ap[(size_t)2*MROWS*3072];
__device__ __align__(16) __nv_bfloat16 g_bp[(size_t)2*2048*1536];

#define EPI_NONE     0
#define EPI_BIAS     1
#define EPI_SOFTPLUS 2
#define EPI_GELU     3

__device__ __forceinline__ float silu_f(float x) {
    return x * (1.0f / (1.0f + __expf(-x)));
}

__device__ __forceinline__ uint32_t smem_u32(const void* p) {
    uint32_t a;
    asm("{ .reg .u64 t; cvta.to.shared.u64 t, %1; cvt.u32.u64 %0, t; }"
        : "=r"(a) : "l"(p));
    return a;
}

// ---------------- baseline-PTX async copy + ldmatrix + mma ---------------------
#define CP_ASYNC16(dst, src) \
    asm volatile("cp.async.cg.shared.global [%0], [%1], 16;" \
                 :: "r"(dst), "l"(src))
#define CP_COMMIT() asm volatile("cp.async.commit_group;" ::: "memory")
#define CP_WAIT(n)  asm volatile("cp.async.wait_group %0;" :: "n"(n) : "memory")

#define LDMATRIX_X4(r0, r1, r2, r3, addr) \
    asm volatile("ldmatrix.sync.aligned.m8n8.x4.shared.b16 {%0,%1,%2,%3}, [%4];" \
                 : "=r"(r0), "=r"(r1), "=r"(r2), "=r"(r3) : "r"(addr))

#define MMA16816(c, a, b0v, b1v) \
    asm volatile("mma.sync.aligned.m16n8k16.row.col.f32.bf16.bf16.f32 " \
                 "{%0,%1,%2,%3}, {%4,%5,%6,%7}, {%8,%9}, {%0,%1,%2,%3};" \
                 : "+f"((c)[0]), "+f"((c)[1]), "+f"((c)[2]), "+f"((c)[3]) \
                 : "r"((a)[0]), "r"((a)[1]), "r"((a)[2]), "r"((a)[3]), \
                   "r"(b0v), "r"(b1v))

// ---------------- split-precision conversion kernels ---------------------------
// A' = [hi | hi | lo] over K, zero-padded to Kp (A2 optionally added first)
__global__ void asplit_k(const float* __restrict__ A, const float* __restrict__ A2,
                         int lda, int K, int Kp, int M, __nv_bfloat16* __restrict__ Ap)
{
    int idx = blockIdx.x * 256 + threadIdx.x;
    if (idx >= M * Kp) return;
    int c = idx % Kp, r = idx / Kp;
    int seg = -1, k = 0;
    if (c < K)          { k = c;       seg = 0; }
    else if (c < 2*K)   { k = c - K;   seg = 0; }
    else if (c < 3*K)   { k = c - 2*K; seg = 1; }
    __nv_bfloat16 o = __float2bfloat16(0.0f);
    if (seg >= 0) {
        float v = A[(size_t)r*lda + k];
        if (A2) v += A2[(size_t)r*lda + k];
        __nv_bfloat16 hi = __float2bfloat16(v);
        o = (seg == 0) ? hi : __float2bfloat16(v - __bfloat162float(hi));
    }
    Ap[idx] = o;
}

// B' (transposed): W[K x N] -> Bp[N x Kp], segments over K: [hi | lo | hi], pad 0
__global__ void bsplit_k(const float* __restrict__ W, int K, int N, int Kp,
                         __nv_bfloat16* __restrict__ Bp)
{
    int idx = blockIdx.x * 256 + threadIdx.x;
    if (idx >= N * Kp) return;
    int c = idx % Kp, n = idx / Kp;
    int seg = -1, k = 0;
    if (c < K)          { k = c;       seg = 0; }
    else if (c < 2*K)   { k = c - K;   seg = 1; }
    else if (c < 3*K)   { k = c - 2*K; seg = 0; }
    __nv_bfloat16 o = __float2bfloat16(0.0f);
    if (seg >= 0) {
        float v = W[(size_t)k*N + n];
        __nv_bfloat16 hi = __float2bfloat16(v);
        o = (seg == 1) ? __float2bfloat16(v - __bfloat162float(hi)) : hi;
    }
    Bp[idx] = o;
}

// ---------------- bf16 mma.sync GEMM (3-stage, batched, optional split-K) ------
// C[M,N] (fp32) = Ap[M x Kp] @ Bp[N x Kp]^T, epilogue fused.
// 256 threads = 8 warps (2 M x 4 N). K-chunks of 32 bf16, 3-stage cp.async ring.
// blockIdx.z encodes (batch, kslice): bt = z / splitK, ks = z % splitK.
// ATOMIC: accumulate into pre-zeroed C via atomicAdd (EPI must be NONE).
template<int BM, int BN, int EPI, bool ATOMIC>
__global__ __launch_bounds__(256)
void mgemm_k(const __nv_bfloat16* __restrict__ Ap, int lda, size_t strA,
             const __nv_bfloat16* __restrict__ Bp, int ldb, size_t strB,
             const float* __restrict__ bias0, const float* __restrict__ bias1,
             float* __restrict__ C, int ldc, size_t strC,
             int NC, int splitK)
{
    constexpr int S   = 3;
    constexpr int MT  = BM/32;        // m16 tiles per warp
    constexpr int NTN = BN/32;        // n8 tiles per warp
    constexpr int CH  = (BM + BN)*80; // bytes per stage

    extern __shared__ char smem[];
    const uint32_t sbase = smem_u32(smem);
    const int tid  = threadIdx.x;
    const int lane = tid & 31, wid = tid >> 5;
    const int wm = wid & 1, wn = wid >> 1;
    const int m0 = blockIdx.y * BM;
    const int n0 = blockIdx.x * BN;
    const int bt = blockIdx.z / splitK;
    const int ksl = blockIdx.z % splitK;

    const __nv_bfloat16* Ab = Ap + (size_t)bt*strA;
    const __nv_bfloat16* Bb = Bp + (size_t)bt*strB;
    float* Cb = C + (size_t)bt*strC;
    const float* bias = bt ? bias1 : bias0;

    const int CNT = NC / splitK;
    const int beg = ksl * CNT;

    float acc[MT][NTN][4];
#pragma unroll
    for (int i = 0; i < MT; i++)
#pragma unroll
        for (int j = 0; j < NTN; j++)
#pragma unroll
            for (int q = 0; q < 4; q++) acc[i][j][q] = 0.0f;

    auto stage = [&](int buf, int ck) {
        uint32_t sA = sbase + buf*CH;
        uint32_t sB = sA + BM*80;
        const __nv_bfloat16* Ag = Ab + (size_t)m0*lda + ck*32;
#pragma unroll
        for (int i = 0; i < BM/64; i++) {
            int q = tid + i*256;
            int r = q >> 2, sg = q & 3;
            CP_ASYNC16(sA + r*80 + sg*16, Ag + (size_t)r*lda + sg*8);
        }
        const __nv_bfloat16* Bg = Bb + (size_t)n0*ldb + ck*32;
#pragma unroll
        for (int i = 0; i < BN/64; i++) {
            int q = tid + i*256;
            int r = q >> 2, sg = q & 3;
            CP_ASYNC16(sB + r*80 + sg*16, Bg + (size_t)r*ldb + sg*8);
        }
    };

    const uint32_t a_off = (uint32_t)((wm*(BM/2) + (lane & 15)) * 80 + (lane >> 4)*16);
    const uint32_t b_off = (uint32_t)(BM*80 +
        (wn*(BN/4) + (lane & 7) + ((lane >> 4) << 3)) * 80 + (((lane >> 3) & 1)*16));

    auto compute = [&](int buf) {
        const uint32_t s0 = sbase + buf*CH;
#pragma unroll
        for (int ks = 0; ks < 2; ks++) {
            uint32_t af[MT][4];
#pragma unroll
            for (int mt = 0; mt < MT; mt++)
                LDMATRIX_X4(af[mt][0], af[mt][1], af[mt][2], af[mt][3],
                            s0 + a_off + (uint32_t)(mt*16*80 + ks*32));
#pragma unroll
            for (int nb = 0; nb < NTN/2; nb++) {
                uint32_t bf[4];
                LDMATRIX_X4(bf[0], bf[1], bf[2], bf[3],
                            s0 + b_off + (uint32_t)(nb*16*80 + ks*32));
#pragma unroll
                for (int mt = 0; mt < MT; mt++) {
                    MMA16816(acc[mt][2*nb+0], af[mt], bf[0], bf[1]);
                    MMA16816(acc[mt][2*nb+1], af[mt], bf[2], bf[3]);
                }
            }
        }
    };

    // 3-stage pipeline
#pragma unroll
    for (int s = 0; s < S-1; s++) {
        if (s < CNT) stage(s, beg + s);
        CP_COMMIT();
    }
    for (int i = 0; i < CNT; i++) {
        CP_WAIT(S-2);
        __syncthreads();
        compute(i % S);
        __syncthreads();
        int nx = i + S - 1;
        if (nx < CNT) stage(nx % S, beg + nx);
        CP_COMMIT();
    }

    // epilogue: fragment c = {C[m][n], C[m][n+1], C[m+8][n], C[m+8][n+1]}
    const int gid = lane >> 2, tig = lane & 3;
#pragma unroll
    for (int mt = 0; mt < MT; mt++) {
#pragma unroll
        for (int nt = 0; nt < NTN; nt++) {
            int m = m0 + wm*(BM/2) + mt*16 + gid;
            int n = n0 + wn*(BN/4) + nt*8 + tig*2;
            float v[4] = {acc[mt][nt][0], acc[mt][nt][1],
                          acc[mt][nt][2], acc[mt][nt][3]};
            if (!ATOMIC) {
#pragma unroll
                for (int q = 0; q < 4; q++) {
                    float w = v[q];
                    if (EPI == EPI_BIAS || EPI == EPI_SOFTPLUS || EPI == EPI_GELU)
                        w += bias[n + (q & 1)];
                    if (EPI == EPI_SOFTPLUS)
                        w = (w > 0.0f) ? (w + log1pf(__expf(-w))) : log1pf(__expf(w));
                    if (EPI == EPI_GELU)
                        w = 0.5f * w * (1.0f + erff(w * 0.70710678118654752f));
                    v[q] = w;
                }
                *reinterpret_cast<float2*>(Cb + (size_t)m*ldc + n)     = make_float2(v[0], v[1]);
                *reinterpret_cast<float2*>(Cb + (size_t)(m+8)*ldc + n) = make_float2(v[2], v[3]);
            } else {
                atomicAdd(Cb + (size_t)m*ldc + n,       v[0]);
                atomicAdd(Cb + (size_t)m*ldc + n + 1,   v[1]);
                atomicAdd(Cb + (size_t)(m+8)*ldc + n,   v[2]);
                atomicAdd(Cb + (size_t)(m+8)*ldc + n+1, v[3]);
            }
        }
    }
}

static inline int round64(int x) { return (x + 63) & ~63; }

template<int BM, int BN, int EPI, bool ATOMIC>
static void launch_mg(const __nv_bfloat16* ap, int Kp, size_t strA,
                      const __nv_bfloat16* bp, size_t strB,
                      const float* b0, const float* b1,
                      float* C, int N, size_t strC, int batch, int splitK)
{
    const int smem = 3*(BM+BN)*80;
    cudaFuncSetAttribute(mgemm_k<BM,BN,EPI,ATOMIC>,
                         cudaFuncAttributeMaxDynamicSharedMemorySize, smem);
    dim3 grid(N/BN, MROWS/BM, batch*splitK);
    mgemm_k<BM,BN,EPI,ATOMIC><<<grid, 256, smem>>>(
        ap, Kp, strA, bp, Kp, strB, b0, b1, C, N, strC, Kp >> 5, splitK);
}

// ---------------- patch gather -------------------------------------------------
__global__ void gather_k(const float* __restrict__ x, float* __restrict__ pin)
{
    int idx = blockIdx.x * blockDim.x + threadIdx.x;
    if (idx >= MROWS*1024) return;
    int k   = idx & 1023;
    int row = idx >> 10;
    int b = row / SEQ, t = row % SEQ;
    int f = t / 100, rem = t % 100;
    int hh = rem / 10, ww = rem % 10;
    int p1 = k >> 6;
    int r2 = k & 63;
    int p2 = r2 >> 2;
    int pf = r2 & 3;
    size_t src = (((size_t)b*32 + (f*4 + pf))*160 + (hh*16 + p1))*160 + (ww*16 + p2);
    pin[idx] = x[src];
}

// ---------------- depthwise causal conv (fwd + reversed) + SiLU ----------------
__global__ void conv_k(const float* __restrict__ xz,
                       const float* __restrict__ wf, const float* __restrict__ bf,
                       const float* __restrict__ wb, const float* __restrict__ bb,
                       float* __restrict__ xcf, float* __restrict__ xcb)
{
    int idx = blockIdx.x * blockDim.x + threadIdx.x;
    if (idx >= MROWS*DINNER) return;
    int d   = idx & (DINNER-1);
    int row = idx >> 10;
    int b = row / SEQ, t = row % SEQ;
    const float* base = xz + (size_t)b*SEQ*2048 + d;

    float w0 = wf[d*4+0], w1 = wf[d*4+1], w2 = wf[d*4+2], w3 = wf[d*4+3];
    float acc = bf[d];
    acc = fmaf(w3, base[(size_t)t*2048], acc);
    if (t >= 1) acc = fmaf(w2, base[(size_t)(t-1)*2048], acc);
    if (t >= 2) acc = fmaf(w1, base[(size_t)(t-2)*2048], acc);
    if (t >= 3) acc = fmaf(w0, base[(size_t)(t-3)*2048], acc);
    xcf[(size_t)row*DINNER + d] = silu_f(acc);

    float v0 = wb[d*4+0], v1 = wb[d*4+1], v2 = wb[d*4+2], v3 = wb[d*4+3];
    float accb = bb[d];
    accb = fmaf(v3, base[(size_t)(SEQ-1-t)*2048], accb);
    if (t >= 1) accb = fmaf(v2, base[(size_t)(SEQ-t)*2048], accb);
    if (t >= 2) accb = fmaf(v1, base[(size_t)(SEQ+1-t)*2048], accb);
    if (t >= 3) accb = fmaf(v0, base[(size_t)(SEQ+2-t)*2048], accb);
    xcb[(size_t)row*DINNER + d] = silu_f(accb);
}

// ---------------- selective-scan (both directions) -----------------------------
__global__ __launch_bounds__(128)
void scan_k(const float* __restrict__ dtf, const float* __restrict__ dtb,
            const float* __restrict__ uf,  const float* __restrict__ ub,
            const float* __restrict__ pf,  const float* __restrict__ pb,
            const float* __restrict__ Af,  const float* __restrict__ Ab,
            const float* __restrict__ Df,  const float* __restrict__ Db,
            const float* __restrict__ xz,
            float* __restrict__ yf, float* __restrict__ yb)
{
    const int d   = blockIdx.x * 128 + threadIdx.x;
    const int b   = blockIdx.y;
    const int dir = blockIdx.z;

    const float* dtp = dir ? dtb : dtf;
    const float* up  = dir ? ub  : uf;
    const float* pp  = dir ? pb  : pf;
    const float* Ap  = dir ? Ab  : Af;
    const float* Dp  = dir ? Db  : Df;
    float*       yp  = dir ? yb  : yf;

    float A[DSTATE];
#pragma unroll
    for (int n = 0; n < DSTATE; n++) A[n] = -expf(Ap[(size_t)d*DSTATE + n]);
    const float Dv = Dp[d];

    bool fast = true;
#pragma unroll
    for (int n = 1; n < DSTATE; n++) {
        float ex = A[0] * (float)(n+1);
        fast = fast && (fabsf(A[n] - ex) <= 1e-4f * fabsf(ex) + 1e-6f);
    }

    float h[DSTATE];
#pragma unroll
    for (int n = 0; n < DSTATE; n++) h[n] = 0.0f;

    int row = b*SEQ;
    float dt_c = dtp[(size_t)row*DINNER + d];
    float u_c  = up [(size_t)row*DINNER + d];
    const float4* bc = reinterpret_cast<const float4*>(pp + (size_t)row*64 + 32);
    float4 Bq[4] = {bc[0], bc[1], bc[2], bc[3]};
    float4 Cq[4] = {bc[4], bc[5], bc[6], bc[7]};
    int orow0 = dir ? (b*SEQ + SEQ-1) : row;
    float z_c = xz[(size_t)orow0*2048 + DINNER + d];

    for (int t = 0; t < SEQ; t++) {
        const float dt = dt_c, u = u_c, zv = z_c;
        float Bv[16] = {Bq[0].x,Bq[0].y,Bq[0].z,Bq[0].w, Bq[1].x,Bq[1].y,Bq[1].z,Bq[1].w,
                        Bq[2].x,Bq[2].y,Bq[2].z,Bq[2].w, Bq[3].x,Bq[3].y,Bq[3].z,Bq[3].w};
        float Cv[16] = {Cq[0].x,Cq[0].y,Cq[0].z,Cq[0].w, Cq[1].x,Cq[1].y,Cq[1].z,Cq[1].w,
                        Cq[2].x,Cq[2].y,Cq[2].z,Cq[2].w, Cq[3].x,Cq[3].y,Cq[3].z,Cq[3].w};
        const int orow = dir ? (b*SEQ + (SEQ-1-t)) : (b*SEQ + t);

        if (t + 1 < SEQ) {
            const int nrow = b*SEQ + t + 1;
            dt_c = dtp[(size_t)nrow*DINNER + d];
            u_c  = up [(size_t)nrow*DINNER + d];
            const float4* nbc = reinterpret_cast<const float4*>(pp + (size_t)nrow*64 + 32);
            Bq[0]=nbc[0]; Bq[1]=nbc[1]; Bq[2]=nbc[2]; Bq[3]=nbc[3];
            Cq[0]=nbc[4]; Cq[1]=nbc[5]; Cq[2]=nbc[6]; Cq[3]=nbc[7];
            const int norow = dir ? (b*SEQ + (SEQ-2-t)) : nrow;
            z_c = xz[(size_t)norow*2048 + DINNER + d];
        }

        float e[16];
        if (fast) {
            float r  = __expf(dt * A[0]);
            float r2 = r*r, r4 = r2*r2, r8 = r4*r4;
            e[0]=r;       e[1]=r2;      e[2]=r2*r;     e[3]=r4;
            e[4]=r4*r;    e[5]=r4*r2;   e[6]=r4*e[2];  e[7]=r8;
            e[8]=r8*r;    e[9]=r8*r2;   e[10]=r8*e[2]; e[11]=r8*r4;
            e[12]=r8*e[4];e[13]=r8*e[5];e[14]=r8*e[6]; e[15]=r8*r8;
        } else {
#pragma unroll
            for (int n = 0; n < 16; n++) e[n] = __expf(dt * A[n]);
        }

        const float du = dt * u;
        float a0=0.f, a1=0.f, a2=0.f, a3=0.f;
#pragma unroll
        for (int n = 0; n < 16; n += 4) {
            h[n+0] = fmaf(e[n+0], h[n+0], du * Bv[n+0]);
            h[n+1] = fmaf(e[n+1], h[n+1], du * Bv[n+1]);
            h[n+2] = fmaf(e[n+2], h[n+2], du * Bv[n+2]);
            h[n+3] = fmaf(e[n+3], h[n+3], du * Bv[n+3]);
            a0 = fmaf(h[n+0], Cv[n+0], a0);
            a1 = fmaf(h[n+1], Cv[n+1], a1);
            a2 = fmaf(h[n+2], Cv[n+2], a2);
            a3 = fmaf(h[n+3], Cv[n+3], a3);
        }
        float y = (a0+a1) + (a2+a3) + u * Dv;
        yp[(size_t)orow*DINNER + d] = y * silu_f(zv);
    }
}

// ---------------- LayerNorm + residual -----------------------------------------
__global__ __launch_bounds__(256)
void ln_res_k(const float* __restrict__ y, const float* __restrict__ g,
              const float* __restrict__ be, float* __restrict__ xt,
              float* __restrict__ outp)
{
    const int row = blockIdx.x;
    const int tid = threadIdx.x;
    const float v0 = y[(size_t)row*DMODEL + tid];
    const float v1 = y[(size_t)row*DMODEL + 256 + tid];
    float s  = v0 + v1;
    float ss = v0*v0 + v1*v1;
#pragma unroll
    for (int off = 16; off > 0; off >>= 1) {
        s  += __shfl_xor_sync(0xffffffffu, s,  off);
        ss += __shfl_xor_sync(0xffffffffu, ss, off);
    }
    __shared__ float sh[2][8];
    const int wid = tid >> 5, lane = tid & 31;
    if (lane == 0) { sh[0][wid] = s; sh[1][wid] = ss; }
    __syncthreads();
    float ts = 0.f, tss = 0.f;
#pragma unroll
    for (int i = 0; i < 8; i++) { ts += sh[0][i]; tss += sh[1][i]; }
    const float mean = ts * (1.0f/DMODEL);
    const float var  = tss * (1.0f/DMODEL) - mean*mean;
    const float rstd = rsqrtf(var + 1e-5f);

    float o0 = (v0 - mean)*rstd*g[tid]     + be[tid]     + xt[(size_t)row*DMODEL + tid];
    float o1 = (v1 - mean)*rstd*g[256+tid] + be[256+tid] + xt[(size_t)row*DMODEL + 256 + tid];
    xt[(size_t)row*DMODEL + tid]       = o0;
    xt[(size_t)row*DMODEL + 256 + tid] = o1;
    if (outp) {
        outp[(size_t)row*DMODEL + tid]       = o0;
        outp[(size_t)row*DMODEL + 256 + tid] = o1;
    }
}

// ---------------- host orchestration -------------------------------------------
extern "C" void kernel_launch(void* const* d_in, const int* in_sizes, int n_in,
                              void* d_out, int out_size)
{
    (void)in_sizes; (void)n_in; (void)out_size;
    const float* x        = (const float*)d_in[0];
    const float* patch_w  = (const float*)d_in[1];
    const float* patch_b  = (const float*)d_in[2];
    const float* in_proj  = (const float*)d_in[3];
    const float* conv_w   = (const float*)d_in[4];
    const float* conv_b   = (const float*)d_in[5];
    const float* xproj_w  = (const float*)d_in[6];
    const float* dt_w     = (const float*)d_in[7];
    const float* dt_bias  = (const float*)d_in[8];
    const float* A_log    = (const float*)d_in[9];
    const float* D_skip   = (const float*)d_in[10];
    const float* conv_wb  = (const float*)d_in[11];
    const float* conv_bb  = (const float*)d_in[12];
    const float* xproj_wb = (const float*)d_in[13];
    const float* dt_wb    = (const float*)d_in[14];
    const float* dt_biasb = (const float*)d_in[15];
    const float* A_logb   = (const float*)d_in[16];
    const float* D_skipb  = (const float*)d_in[17];
    const float* out_proj = (const float*)d_in[18];
    const float* ln1_g    = (const float*)d_in[19];
    const float* ln1_b    = (const float*)d_in[20];
    const float* fc1_w    = (const float*)d_in[21];
    const float* fc1_b    = (const float*)d_in[22];
    const float* fc2_w    = (const float*)d_in[23];
    const float* fc2_b    = (const float*)d_in[24];
    const float* ln2_g    = (const float*)d_in[25];
    const float* ln2_b    = (const float*)d_in[26];
    float* out = (float*)d_out;

    float *pin, *xt, *xz, *xc, *prj, *dtv, *yf, *yb, *t512, *mid;
    __nv_bfloat16 *ap, *bp;
    cudaGetSymbolAddress((void**)&pin,  g_pin);
    cudaGetSymbolAddress((void**)&xt,   g_xt);
    cudaGetSymbolAddress((void**)&xz,   g_xz);
    cudaGetSymbolAddress((void**)&xc,   g_xc);
    cudaGetSymbolAddress((void**)&prj,  g_prj);
    cudaGetSymbolAddress((void**)&dtv,  g_dt);
    cudaGetSymbolAddress((void**)&yf,   g_yf);
    cudaGetSymbolAddress((void**)&yb,   g_yb);
    cudaGetSymbolAddress((void**)&t512, g_t512);
    cudaGetSymbolAddress((void**)&mid,  g_mid);
    cudaGetSymbolAddress((void**)&ap,   g_ap);
    cudaGetSymbolAddress((void**)&bp,   g_bp);

    float* xcf = xc;
    float* xcb = xc + (size_t)MROWS*DINNER;
    float* prjf = prj;
    float* prjb = prj + (size_t)MROWS*64;
    float* dtf = dtv;
    float* dtb = dtv + (size_t)MROWS*DINNER;

    // ---- patch embed: pin[6400x1024] @ patch_w[1024x512] + b  (BN=64 -> 400 CTAs)
    gather_k<<<(MROWS*1024 + 255)/256, 256>>>(x, pin);
    {
        const int Kp = round64(3*1024);   // 3072
        asplit_k<<<(MROWS*Kp + 255)/256, 256>>>(pin, nullptr, 1024, 1024, Kp, MROWS, ap);
        bsplit_k<<<(512*Kp + 255)/256, 256>>>(patch_w, 1024, 512, Kp, bp);
        launch_mg<128,64,EPI_BIAS,false>(ap, Kp, 0, bp, 0, patch_b, nullptr,
                                         xt, 512, 0, 1, 1);
    }

    for (int l = 0; l < NLAYER; l++) {
        // ---- in_proj: xz = xt @ W[512x2048]  (grid 800)
        {
            const int Kp = round64(3*512);   // 1536
            asplit_k<<<(MROWS*Kp + 255)/256, 256>>>(xt, nullptr, 512, 512, Kp, MROWS, ap);
            bsplit_k<<<(2048*Kp + 255)/256, 256>>>(in_proj + (size_t)l*512*2048,
                                                   512, 2048, Kp, bp);
            launch_mg<128,128,EPI_NONE,false>(ap, Kp, 0, bp, 0, nullptr, nullptr,
                                              xz, 2048, 0, 1, 1);
        }

        conv_k<<<(MROWS*DINNER + 255)/256, 256>>>(
            xz,
            conv_w  + (size_t)l*DINNER*DCONV, conv_b  + (size_t)l*DINNER,
            conv_wb + (size_t)l*DINNER*DCONV, conv_bb + (size_t)l*DINNER,
            xcf, xcb);

        // ---- x-proj (N=64), batched fwd+bwd, split-K x4, atomic into zeroed prj
        {
            const int Kp = round64(3*DINNER);   // 3072
            const size_t sAp = (size_t)MROWS*Kp;
            asplit_k<<<(MROWS*Kp + 255)/256, 256>>>(xcf, nullptr, DINNER, DINNER, Kp, MROWS, ap);
            asplit_k<<<(MROWS*Kp + 255)/256, 256>>>(xcb, nullptr, DINNER, DINNER, Kp, MROWS, ap + sAp);
            bsplit_k<<<(64*Kp + 255)/256, 256>>>(xproj_w  + (size_t)l*DINNER*64, DINNER, 64, Kp, bp);
            bsplit_k<<<(64*Kp + 255)/256, 256>>>(xproj_wb + (size_t)l*DINNER*64, DINNER, 64, Kp,
                                                 bp + (size_t)64*Kp);
            cudaMemsetAsync(prj, 0, (size_t)2*MROWS*64*sizeof(float), 0);
            launch_mg<128,64,EPI_NONE,true>(ap, Kp, sAp, bp, (size_t)64*Kp,
                                            nullptr, nullptr,
                                            prj, 64, (size_t)MROWS*64, 2, 4);
        }

        // ---- dt = softplus(prj[:, :32] @ dt_w[32x1024] + bias), batched (grid 800)
        {
            const int Kp = round64(3*DTRANK);   // 96
            const size_t sAp = (size_t)MROWS*Kp;
            asplit_k<<<(MROWS*Kp + 255)/256, 256>>>(prjf, nullptr, 64, DTRANK, Kp, MROWS, ap);
            asplit_k<<<(MROWS*Kp + 255)/256, 256>>>(prjb, nullptr, 64, DTRANK, Kp, MROWS, ap + sAp);
            bsplit_k<<<(DINNER*Kp + 255)/256, 256>>>(dt_w  + (size_t)l*DTRANK*DINNER,
                                                     DTRANK, DINNER, Kp, bp);
            bsplit_k<<<(DINNER*Kp + 255)/256, 256>>>(dt_wb + (size_t)l*DTRANK*DINNER,
                                                     DTRANK, DINNER, Kp, bp + (size_t)DINNER*Kp);
            launch_mg<128,128,EPI_SOFTPLUS,false>(ap, Kp, sAp, bp, (size_t)DINNER*Kp,
                                                  dt_bias  + (size_t)l*DINNER,
                                                  dt_biasb + (size_t)l*DINNER,
                                                  dtv, DINNER, (size_t)MROWS*DINNER, 2, 1);
        }

        scan_k<<<dim3(DINNER/128, BATCH, 2), 128>>>(
            dtf, dtb, xcf, xcb, prjf, prjb,
            A_log  + (size_t)l*DINNER*DSTATE, A_logb + (size_t)l*DINNER*DSTATE,
            D_skip + (size_t)l*DINNER,        D_skipb + (size_t)l*DINNER,
            xz, yf, yb);

        // ---- out_proj on (yf + yb)  (BN=64 -> 400 CTAs)
        {
            const int Kp = round64(3*DINNER);   // 3072
            asplit_k<<<(MROWS*Kp + 255)/256, 256>>>(yf, yb, DINNER, DINNER, Kp, MROWS, ap);
            bsplit_k<<<(DMODEL*Kp + 255)/256, 256>>>(out_proj + (size_t)l*DINNER*DMODEL,
                                                     DINNER, DMODEL, Kp, bp);
            launch_mg<128,64,EPI_NONE,false>(ap, Kp, 0, bp, 0, nullptr, nullptr,
                                             t512, DMODEL, 0, 1, 1);
        }

        ln_res_k<<<MROWS, 256>>>(t512, ln1_g + (size_t)l*DMODEL,
                                 ln1_b + (size_t)l*DMODEL, xt, nullptr);

        // ---- fc1 (grid 400)
        {
            const int Kp = round64(3*DMODEL);   // 1536
            asplit_k<<<(MROWS*Kp + 255)/256, 256>>>(xt, nullptr, DMODEL, DMODEL, Kp, MROWS, ap);
            bsplit_k<<<(1024*Kp + 255)/256, 256>>>(fc1_w + (size_t)l*DMODEL*1024,
                                                   DMODEL, 1024, Kp, bp);
            launch_mg<128,128,EPI_GELU,false>(ap, Kp, 0, bp, 0,
                                              fc1_b + (size_t)l*1024, nullptr,
                                              mid, 1024, 0, 1, 1);
        }
        // ---- fc2 (BN=64 -> 400 CTAs)
        {
            const int Kp = round64(3*1024);   // 3072
            asplit_k<<<(MROWS*Kp + 255)/256, 256>>>(mid, nullptr, 1024, 1024, Kp, MROWS, ap);
            bsplit_k<<<(DMODEL*Kp + 255)/256, 256>>>(fc2_w + (size_t)l*1024*DMODEL,
                                                     1024, DMODEL, Kp, bp);
            launch_mg<128,64,EPI_BIAS,false>(ap, Kp, 0, bp, 0,
                                             fc2_b + (size_t)l*DMODEL, nullptr,
                                             t512, DMODEL, 0, 1, 1);
        }

        ln_res_k<<<MROWS, 256>>>(t512, ln2_g + (size_t)l*DMODEL,
                                 ln2_b + (size_t)l*DMODEL, xt,
                                 out + (size_t)l*MROWS*DMODEL);
    }
}

// round 15
// speedup vs baseline: 1.7793x; 1.1822x over previous
#include <cuda_runtime.h>
#include <cuda_bf16.h>
#include <math.h>
#include <stdint.h>

#define NLAYER 8
#define DMODEL 512
#define DINNER 1024
#define DSTATE 16
#define DCONV  4
#define DTRANK 32
#define BATCH  8
#define SEQ    800
#define MROWS  (BATCH*SEQ)   // 6400

// ---------------- scratch (static device globals) ------------------------------
__device__ float g_pin [MROWS*1024];
__device__ float g_xt  [MROWS*DMODEL];
__device__ float g_xz  [MROWS*2*DINNER];
__device__ float g_xc  [2*MROWS*DINNER];   // fwd | bwd conv outputs
__device__ float g_prj [2*MROWS*64];       // fwd | bwd xproj outputs
__device__ float g_dt  [2*MROWS*DINNER];   // fwd | bwd dt
__device__ float g_yf  [MROWS*DINNER];
__device__ float g_yb  [MROWS*DINNER];
__device__ float g_t512[MROWS*DMODEL];
__device__ float g_mid [MROWS*DINNER];
// bf16 split operands [hi|lo] (16B aligned for cp.async), 2 batches
__device__ __align__(16) __nv_bfloat16 g_ap[(size_t)2*MROWS*2048];
__device__ __align__(16) __nv_bfloat16 g_bp[(size_t)2*2048*2048];

#define EPI_NONE     0
#define EPI_BIAS     1
#define EPI_SOFTPLUS 2
#define EPI_GELU     3

__device__ __forceinline__ float silu_f(float x) {
    return x * (1.0f / (1.0f + __expf(-x)));
}

__device__ __forceinline__ uint32_t smem_u32(const void* p) {
    uint32_t a;
    asm("{ .reg .u64 t; cvta.to.shared.u64 t, %1; cvt.u32.u64 %0, t; }"
        : "=r"(a) : "l"(p));
    return a;
}

// ---------------- baseline-PTX async copy + ldmatrix + mma ---------------------
#define CP_ASYNC16(dst, src) \
    asm volatile("cp.async.cg.shared.global [%0], [%1], 16;" \
                 :: "r"(dst), "l"(src))
#define CP_COMMIT() asm volatile("cp.async.commit_group;" ::: "memory")
#define CP_WAIT(n)  asm volatile("cp.async.wait_group %0;" :: "n"(n) : "memory")

#define LDMATRIX_X4(r0, r1, r2, r3, addr) \
    asm volatile("ldmatrix.sync.aligned.m8n8.x4.shared.b16 {%0,%1,%2,%3}, [%4];" \
                 : "=r"(r0), "=r"(r1), "=r"(r2), "=r"(r3) : "r"(addr))

#define MMA16816(c, a, b0v, b1v) \
    asm volatile("mma.sync.aligned.m16n8k16.row.col.f32.bf16.bf16.f32 " \
                 "{%0,%1,%2,%3}, {%4,%5,%6,%7}, {%8,%9}, {%0,%1,%2,%3};" \
                 : "+f"((c)[0]), "+f"((c)[1]), "+f"((c)[2]), "+f"((c)[3]) \
                 : "r"((a)[0]), "r"((a)[1]), "r"((a)[2]), "r"((a)[3]), \
                   "r"(b0v), "r"(b1v))

// ---------------- split-precision conversion kernels ---------------------------
// A' = [hi | lo] over K (2K cols), A2 optionally added first.
__global__ void asplit_k(const float* __restrict__ A, const float* __restrict__ A2,
                         int lda, int K, int M, __nv_bfloat16* __restrict__ Ap)
{
    int idx = blockIdx.x * 256 + threadIdx.x;
    if (idx >= M * K) return;
    int k = idx % K, r = idx / K;
    float v = A[(size_t)r*lda + k];
    if (A2) v += A2[(size_t)r*lda + k];
    __nv_bfloat16 hi = __float2bfloat16(v);
    __nv_bfloat16 lo = __float2bfloat16(v - __bfloat162float(hi));
    __nv_bfloat16* row = Ap + (size_t)r*(2*K);
    row[k]     = hi;
    row[K + k] = lo;
}

// B' (transposed): W[K x N] -> Bp[N x 2K] as [hi | lo]
__global__ void bsplit_k(const float* __restrict__ W, int K, int N,
                         __nv_bfloat16* __restrict__ Bp)
{
    int idx = blockIdx.x * 256 + threadIdx.x;
    if (idx >= N * K) return;
    int k = idx % K, n = idx / K;
    float v = W[(size_t)k*N + n];
    __nv_bfloat16 hi = __float2bfloat16(v);
    __nv_bfloat16 lo = __float2bfloat16(v - __bfloat162float(hi));
    __nv_bfloat16* row = Bp + (size_t)n*(2*K);
    row[k]     = hi;
    row[K + k] = lo;
}

// ---------------- bf16 mma.sync GEMM (4-stage single-sync, 3-pass split) -------
// C[M,N] (fp32) = A @ B^T computed as Ahi*Bhi + Ahi*Blo + Alo*Bhi over compact
// [hi|lo] operands (lda = ldb = 2K). 256 threads = 8 warps (2 M x 4 N).
// blockIdx.z encodes (batch, kslice). ATOMIC: atomicAdd into pre-zeroed C.
template<int BM, int BN, int EPI, bool ATOMIC>
__global__ __launch_bounds__(256)
void mgemm_k(const __nv_bfloat16* __restrict__ Ap, size_t strA,
             const __nv_bfloat16* __restrict__ Bp, size_t strB,
             const float* __restrict__ bias0, const float* __restrict__ bias1,
             float* __restrict__ C, int ldc, size_t strC,
             int Kd, int splitK)
{
    constexpr int S   = 4;
    constexpr int MT  = BM/32;        // m16 tiles per warp
    constexpr int NTN = BN/32;        // n8 tiles per warp
    constexpr int CH  = (BM + BN)*80; // bytes per stage

    extern __shared__ char smem[];
    const uint32_t sbase = smem_u32(smem);
    const int tid  = threadIdx.x;
    const int lane = tid & 31, wid = tid >> 5;
    const int wm = wid & 1, wn = wid >> 1;
    const int m0 = blockIdx.y * BM;
    const int n0 = blockIdx.x * BN;
    const int bt = blockIdx.z / splitK;
    const int ksl = blockIdx.z % splitK;

    const int ld = 2*Kd;                 // row stride of compact operands
    const int KC = Kd >> 5;              // 32-chunks per pass
    const int NC3 = 3*KC;
    const int CNT = NC3 / splitK;
    const int beg = ksl * CNT;

    const __nv_bfloat16* Ab = Ap + (size_t)bt*strA;
    const __nv_bfloat16* Bb = Bp + (size_t)bt*strB;
    float* Cb = C + (size_t)bt*strC;
    const float* bias = bt ? bias1 : bias0;

    float acc[MT][NTN][4];
#pragma unroll
    for (int i = 0; i < MT; i++)
#pragma unroll
        for (int j = 0; j < NTN; j++)
#pragma unroll
            for (int q = 0; q < 4; q++) acc[i][j][q] = 0.0f;

    // chunk -> global k offsets: pass 0 (hi,hi), 1 (hi,lo), 2 (lo,hi)
    auto stage = [&](int buf, int c) {
        int p = c / KC, kk = c - p*KC;
        int ak = ((p == 2) ? Kd : 0) + kk*32;
        int bk = ((p == 1) ? Kd : 0) + kk*32;
        uint32_t sA = sbase + buf*CH;
        uint32_t sB = sA + BM*80;
        const __nv_bfloat16* Ag = Ab + (size_t)m0*ld + ak;
#pragma unroll
        for (int i = 0; i < BM/64; i++) {
            int q = tid + i*256;
            int r = q >> 2, sg = q & 3;
            CP_ASYNC16(sA + r*80 + sg*16, Ag + (size_t)r*ld + sg*8);
        }
        const __nv_bfloat16* Bg = Bb + (size_t)n0*ld + bk;
#pragma unroll
        for (int i = 0; i < BN/64; i++) {
            int q = tid + i*256;
            int r = q >> 2, sg = q & 3;
            CP_ASYNC16(sB + r*80 + sg*16, Bg + (size_t)r*ld + sg*8);
        }
    };

    const uint32_t a_off = (uint32_t)((wm*(BM/2) + (lane & 15)) * 80 + (lane >> 4)*16);
    const uint32_t b_off = (uint32_t)(BM*80 +
        (wn*(BN/4) + (lane & 7) + ((lane >> 4) << 3)) * 80 + (((lane >> 3) & 1)*16));

    auto compute = [&](int buf) {
        const uint32_t s0 = sbase + buf*CH;
#pragma unroll
        for (int ks = 0; ks < 2; ks++) {
            uint32_t af[MT][4];
#pragma unroll
            for (int mt = 0; mt < MT; mt++)
                LDMATRIX_X4(af[mt][0], af[mt][1], af[mt][2], af[mt][3],
                            s0 + a_off + (uint32_t)(mt*16*80 + ks*32));
#pragma unroll
            for (int nb = 0; nb < NTN/2; nb++) {
                uint32_t bf[4];
                LDMATRIX_X4(bf[0], bf[1], bf[2], bf[3],
                            s0 + b_off + (uint32_t)(nb*16*80 + ks*32));
#pragma unroll
                for (int mt = 0; mt < MT; mt++) {
                    MMA16816(acc[mt][2*nb+0], af[mt], bf[0], bf[1]);
                    MMA16816(acc[mt][2*nb+1], af[mt], bf[2], bf[3]);
                }
            }
        }
    };

    // 4-stage pipeline, single sync per chunk
#pragma unroll
    for (int s = 0; s < S-1; s++) {
        if (s < CNT) stage(s, beg + s);
        CP_COMMIT();
    }
    for (int i = 0; i < CNT; i++) {
        CP_WAIT(S-2);
        __syncthreads();          // chunk i resident; iter i-1 compute finished
        int nx = i + S - 1;
        if (nx < CNT) stage(nx & 3, beg + nx);
        CP_COMMIT();
        compute(i & 3);
    }

    // epilogue: fragment c = {C[m][n], C[m][n+1], C[m+8][n], C[m+8][n+1]}
    const int gid = lane >> 2, tig = lane & 3;
#pragma unroll
    for (int mt = 0; mt < MT; mt++) {
#pragma unroll
        for (int nt = 0; nt < NTN; nt++) {
            int m = m0 + wm*(BM/2) + mt*16 + gid;
            int n = n0 + wn*(BN/4) + nt*8 + tig*2;
            float v[4] = {acc[mt][nt][0], acc[mt][nt][1],
                          acc[mt][nt][2], acc[mt][nt][3]};
            if (!ATOMIC) {
#pragma unroll
                for (int q = 0; q < 4; q++) {
                    float w = v[q];
                    if (EPI == EPI_BIAS || EPI == EPI_SOFTPLUS || EPI == EPI_GELU)
                        w += bias[n + (q & 1)];
                    if (EPI == EPI_SOFTPLUS)
                        w = (w > 0.0f) ? (w + log1pf(__expf(-w))) : log1pf(__expf(w));
                    if (EPI == EPI_GELU)
                        w = 0.5f * w * (1.0f + erff(w * 0.70710678118654752f));
                    v[q] = w;
                }
                *reinterpret_cast<float2*>(Cb + (size_t)m*ldc + n)     = make_float2(v[0], v[1]);
                *reinterpret_cast<float2*>(Cb + (size_t)(m+8)*ldc + n) = make_float2(v[2], v[3]);
            } else {
                atomicAdd(Cb + (size_t)m*ldc + n,       v[0]);
                atomicAdd(Cb + (size_t)m*ldc + n + 1,   v[1]);
                atomicAdd(Cb + (size_t)(m+8)*ldc + n,   v[2]);
                atomicAdd(Cb + (size_t)(m+8)*ldc + n+1, v[3]);
            }
        }
    }
}

template<int BM, int BN, int EPI, bool ATOMIC>
static void launch_mg(const __nv_bfloat16* ap, size_t strA,
                      const __nv_bfloat16* bp, size_t strB,
                      const float* b0, const float* b1,
                      float* C, int N, size_t strC,
                      int batch, int splitK, int Kd)
{
    const int smem = 4*(BM+BN)*80;
    cudaFuncSetAttribute(mgemm_k<BM,BN,EPI,ATOMIC>,
                         cudaFuncAttributeMaxDynamicSharedMemorySize, smem);
    dim3 grid(N/BN, MROWS/BM, batch*splitK);
    mgemm_k<BM,BN,EPI,ATOMIC><<<grid, 256, smem>>>(
        ap, strA, bp, strB, b0, b1, C, N, strC, Kd, splitK);
}

// ---------------- patch gather -------------------------------------------------
__global__ void gather_k(const float* __restrict__ x, float* __restrict__ pin)
{
    int idx = blockIdx.x * blockDim.x + threadIdx.x;
    if (idx >= MROWS*1024) return;
    int k   = idx & 1023;
    int row = idx >> 10;
    int b = row / SEQ, t = row % SEQ;
    int f = t / 100, rem = t % 100;
    int hh = rem / 10, ww = rem % 10;
    int p1 = k >> 6;
    int r2 = k & 63;
    int p2 = r2 >> 2;
    int pf = r2 & 3;
    size_t src = (((size_t)b*32 + (f*4 + pf))*160 + (hh*16 + p1))*160 + (ww*16 + p2);
    pin[idx] = x[src];
}

// ---------------- depthwise causal conv (fwd + reversed) + SiLU ----------------
__global__ void conv_k(const float* __restrict__ xz,
                       const float* __restrict__ wf, const float* __restrict__ bf,
                       const float* __restrict__ wb, const float* __restrict__ bb,
                       float* __restrict__ xcf, float* __restrict__ xcb)
{
    int idx = blockIdx.x * blockDim.x + threadIdx.x;
    if (idx >= MROWS*DINNER) return;
    int d   = idx & (DINNER-1);
    int row = idx >> 10;
    int b = row / SEQ, t = row % SEQ;
    const float* base = xz + (size_t)b*SEQ*2048 + d;

    float w0 = wf[d*4+0], w1 = wf[d*4+1], w2 = wf[d*4+2], w3 = wf[d*4+3];
    float acc = bf[d];
    acc = fmaf(w3, base[(size_t)t*2048], acc);
    if (t >= 1) acc = fmaf(w2, base[(size_t)(t-1)*2048], acc);
    if (t >= 2) acc = fmaf(w1, base[(size_t)(t-2)*2048], acc);
    if (t >= 3) acc = fmaf(w0, base[(size_t)(t-3)*2048], acc);
    xcf[(size_t)row*DINNER + d] = silu_f(acc);

    float v0 = wb[d*4+0], v1 = wb[d*4+1], v2 = wb[d*4+2], v3 = wb[d*4+3];
    float accb = bb[d];
    accb = fmaf(v3, base[(size_t)(SEQ-1-t)*2048], accb);
    if (t >= 1) accb = fmaf(v2, base[(size_t)(SEQ-t)*2048], accb);
    if (t >= 2) accb = fmaf(v1, base[(size_t)(SEQ+1-t)*2048], accb);
    if (t >= 3) accb = fmaf(v0, base[(size_t)(SEQ+2-t)*2048], accb);
    xcb[(size_t)row*DINNER + d] = silu_f(accb);
}

// ---------------- selective-scan (both directions) -----------------------------
__global__ __launch_bounds__(128)
void scan_k(const float* __restrict__ dtf, const float* __restrict__ dtb,
            const float* __restrict__ uf,  const float* __restrict__ ub,
            const float* __restrict__ pf,  const float* __restrict__ pb,
            const float* __restrict__ Af,  const float* __restrict__ Ab,
            const float* __restrict__ Df,  const float* __restrict__ Db,
            const float* __restrict__ xz,
            float* __restrict__ yf, float* __restrict__ yb)
{
    const int d   = blockIdx.x * 128 + threadIdx.x;
    const int b   = blockIdx.y;
    const int dir = blockIdx.z;

    const float* dtp = dir ? dtb : dtf;
    const float* up  = dir ? ub  : uf;
    const float* pp  = dir ? pb  : pf;
    const float* Ap  = dir ? Ab  : Af;
    const float* Dp  = dir ? Db  : Df;
    float*       yp  = dir ? yb  : yf;

    float A[DSTATE];
#pragma unroll
    for (int n = 0; n < DSTATE; n++) A[n] = -expf(Ap[(size_t)d*DSTATE + n]);
    const float Dv = Dp[d];

    bool fast = true;
#pragma unroll
    for (int n = 1; n < DSTATE; n++) {
        float ex = A[0] * (float)(n+1);
        fast = fast && (fabsf(A[n] - ex) <= 1e-4f * fabsf(ex) + 1e-6f);
    }

    float h[DSTATE];
#pragma unroll
    for (int n = 0; n < DSTATE; n++) h[n] = 0.0f;

    int row = b*SEQ;
    float dt_c = dtp[(size_t)row*DINNER + d];
    float u_c  = up [(size_t)row*DINNER + d];
    const float4* bc = reinterpret_cast<const float4*>(pp + (size_t)row*64 + 32);
    float4 Bq[4] = {bc[0], bc[1], bc[2], bc[3]};
    float4 Cq[4] = {bc[4], bc[5], bc[6], bc[7]};
    int orow0 = dir ? (b*SEQ + SEQ-1) : row;
    float z_c = xz[(size_t)orow0*2048 + DINNER + d];

    for (int t = 0; t < SEQ; t++) {
        const float dt = dt_c, u = u_c, zv = z_c;
        float Bv[16] = {Bq[0].x,Bq[0].y,Bq[0].z,Bq[0].w, Bq[1].x,Bq[1].y,Bq[1].z,Bq[1].w,
                        Bq[2].x,Bq[2].y,Bq[2].z,Bq[2].w, Bq[3].x,Bq[3].y,Bq[3].z,Bq[3].w};
        float Cv[16] = {Cq[0].x,Cq[0].y,Cq[0].z,Cq[0].w, Cq[1].x,Cq[1].y,Cq[1].z,Cq[1].w,
                        Cq[2].x,Cq[2].y,Cq[2].z,Cq[2].w, Cq[3].x,Cq[3].y,Cq[3].z,Cq[3].w};
        const int orow = dir ? (b*SEQ + (SEQ-1-t)) : (b*SEQ + t);

        if (t + 1 < SEQ) {
            const int nrow = b*SEQ + t + 1;
            dt_c = dtp[(size_t)nrow*DINNER + d];
            u_c  = up [(size_t)nrow*DINNER + d];
            const float4* nbc = reinterpret_cast<const float4*>(pp + (size_t)nrow*64 + 32);
            Bq[0]=nbc[0]; Bq[1]=nbc[1]; Bq[2]=nbc[2]; Bq[3]=nbc[3];
            Cq[0]=nbc[4]; Cq[1]=nbc[5]; Cq[2]=nbc[6]; Cq[3]=nbc[7];
            const int norow = dir ? (b*SEQ + (SEQ-2-t)) : nrow;
            z_c = xz[(size_t)norow*2048 + DINNER + d];
        }

        float e[16];
        if (fast) {
            float r  = __expf(dt * A[0]);
            float r2 = r*r, r4 = r2*r2, r8 = r4*r4;
            e[0]=r;       e[1]=r2;      e[2]=r2*r;     e[3]=r4;
            e[4]=r4*r;    e[5]=r4*r2;   e[6]=r4*e[2];  e[7]=r8;
            e[8]=r8*r;    e[9]=r8*r2;   e[10]=r8*e[2]; e[11]=r8*r4;
            e[12]=r8*e[4];e[13]=r8*e[5];e[14]=r8*e[6]; e[15]=r8*r8;
        } else {
#pragma unroll
            for (int n = 0; n < 16; n++) e[n] = __expf(dt * A[n]);
        }

        const float du = dt * u;
        float a0=0.f, a1=0.f, a2=0.f, a3=0.f;
#pragma unroll
        for (int n = 0; n < 16; n += 4) {
            h[n+0] = fmaf(e[n+0], h[n+0], du * Bv[n+0]);
            h[n+1] = fmaf(e[n+1], h[n+1], du * Bv[n+1]);
            h[n+2] = fmaf(e[n+2], h[n+2], du * Bv[n+2]);
            h[n+3] = fmaf(e[n+3], h[n+3], du * Bv[n+3]);
            a0 = fmaf(h[n+0], Cv[n+0], a0);
            a1 = fmaf(h[n+1], Cv[n+1], a1);
            a2 = fmaf(h[n+2], Cv[n+2], a2);
            a3 = fmaf(h[n+3], Cv[n+3], a3);
        }
        float y = (a0+a1) + (a2+a3) + u * Dv;
        yp[(size_t)orow*DINNER + d] = y * silu_f(zv);
    }
}

// ---------------- LayerNorm + residual -----------------------------------------
__global__ __launch_bounds__(256)
void ln_res_k(const float* __restrict__ y, const float* __restrict__ g,
              const float* __restrict__ be, float* __restrict__ xt,
              float* __restrict__ outp)
{
    const int row = blockIdx.x;
    const int tid = threadIdx.x;
    const float v0 = y[(size_t)row*DMODEL + tid];
    const float v1 = y[(size_t)row*DMODEL + 256 + tid];
    float s  = v0 + v1;
    float ss = v0*v0 + v1*v1;
#pragma unroll
    for (int off = 16; off > 0; off >>= 1) {
        s  += __shfl_xor_sync(0xffffffffu, s,  off);
        ss += __shfl_xor_sync(0xffffffffu, ss, off);
    }
    __shared__ float sh[2][8];
    const int wid = tid >> 5, lane = tid & 31;
    if (lane == 0) { sh[0][wid] = s; sh[1][wid] = ss; }
    __syncthreads();
    float ts = 0.f, tss = 0.f;
#pragma unroll
    for (int i = 0; i < 8; i++) { ts += sh[0][i]; tss += sh[1][i]; }
    const float mean = ts * (1.0f/DMODEL);
    const float var  = tss * (1.0f/DMODEL) - mean*mean;
    const float rstd = rsqrtf(var + 1e-5f);

    float o0 = (v0 - mean)*rstd*g[tid]     + be[tid]     + xt[(size_t)row*DMODEL + tid];
    float o1 = (v1 - mean)*rstd*g[256+tid] + be[256+tid] + xt[(size_t)row*DMODEL + 256 + tid];
    xt[(size_t)row*DMODEL + tid]       = o0;
    xt[(size_t)row*DMODEL + 256 + tid] = o1;
    if (outp) {
        outp[(size_t)row*DMODEL + tid]       = o0;
        outp[(size_t)row*DMODEL + 256 + tid] = o1;
    }
}

// ---------------- host orchestration -------------------------------------------
extern "C" void kernel_launch(void* const* d_in, const int* in_sizes, int n_in,
                              void* d_out, int out_size)
{
    (void)in_sizes; (void)n_in; (void)out_size;
    const float* x        = (const float*)d_in[0];
    const float* patch_w  = (const float*)d_in[1];
    const float* patch_b  = (const float*)d_in[2];
    const float* in_proj  = (const float*)d_in[3];
    const float* conv_w   = (const float*)d_in[4];
    const float* conv_b   = (const float*)d_in[5];
    const float* xproj_w  = (const float*)d_in[6];
    const float* dt_w     = (const float*)d_in[7];
    const float* dt_bias  = (const float*)d_in[8];
    const float* A_log    = (const float*)d_in[9];
    const float* D_skip   = (const float*)d_in[10];
    const float* conv_wb  = (const float*)d_in[11];
    const float* conv_bb  = (const float*)d_in[12];
    const float* xproj_wb = (const float*)d_in[13];
    const float* dt_wb    = (const float*)d_in[14];
    const float* dt_biasb = (const float*)d_in[15];
    const float* A_logb   = (const float*)d_in[16];
    const float* D_skipb  = (const float*)d_in[17];
    const float* out_proj = (const float*)d_in[18];
    const float* ln1_g    = (const float*)d_in[19];
    const float* ln1_b    = (const float*)d_in[20];
    const float* fc1_w    = (const float*)d_in[21];
    const float* fc1_b    = (const float*)d_in[22];
    const float* fc2_w    = (const float*)d_in[23];
    const float* fc2_b    = (const float*)d_in[24];
    const float* ln2_g    = (const float*)d_in[25];
    const float* ln2_b    = (const float*)d_in[26];
    float* out = (float*)d_out;

    float *pin, *xt, *xz, *xc, *prj, *dtv, *yf, *yb, *t512, *mid;
    __nv_bfloat16 *ap, *bp;
    cudaGetSymbolAddress((void**)&pin,  g_pin);
    cudaGetSymbolAddress((void**)&xt,   g_xt);
    cudaGetSymbolAddress((void**)&xz,   g_xz);
    cudaGetSymbolAddress((void**)&xc,   g_xc);
    cudaGetSymbolAddress((void**)&prj,  g_prj);
    cudaGetSymbolAddress((void**)&dtv,  g_dt);
    cudaGetSymbolAddress((void**)&yf,   g_yf);
    cudaGetSymbolAddress((void**)&yb,   g_yb);
    cudaGetSymbolAddress((void**)&t512, g_t512);
    cudaGetSymbolAddress((void**)&mid,  g_mid);
    cudaGetSymbolAddress((void**)&ap,   g_ap);
    cudaGetSymbolAddress((void**)&bp,   g_bp);

    float* xcf = xc;
    float* xcb = xc + (size_t)MROWS*DINNER;
    float* prjf = prj;
    float* prjb = prj + (size_t)MROWS*64;
    float* dtf = dtv;
    float* dtb = dtv + (size_t)MROWS*DINNER;

    // ---- patch embed: pin[6400x1024] @ patch_w[1024x512] + b
    gather_k<<<(MROWS*1024 + 255)/256, 256>>>(x, pin);
    {
        const int K = 1024;
        asplit_k<<<(MROWS*K + 255)/256, 256>>>(pin, nullptr, K, K, MROWS, ap);
        bsplit_k<<<(512*K + 255)/256, 256>>>(patch_w, K, 512, bp);
        launch_mg<128,64,EPI_BIAS,false>(ap, 0, bp, 0, patch_b, nullptr,
                                         xt, 512, 0, 1, 1, K);
    }

    for (int l = 0; l < NLAYER; l++) {
        // ---- in_proj: xz = xt @ W[512x2048]
        {
            const int K = 512;
            asplit_k<<<(MROWS*K + 255)/256, 256>>>(xt, nullptr, K, K, MROWS, ap);
            bsplit_k<<<(2048*K + 255)/256, 256>>>(in_proj + (size_t)l*512*2048,
                                                  K, 2048, bp);
            launch_mg<128,128,EPI_NONE,false>(ap, 0, bp, 0, nullptr, nullptr,
                                              xz, 2048, 0, 1, 1, K);
        }

        conv_k<<<(MROWS*DINNER + 255)/256, 256>>>(
            xz,
            conv_w  + (size_t)l*DINNER*DCONV, conv_b  + (size_t)l*DINNER,
            conv_wb + (size_t)l*DINNER*DCONV, conv_bb + (size_t)l*DINNER,
            xcf, xcb);

        // ---- x-proj (N=64), batched fwd+bwd, split-K x4, atomic into zeroed prj
        {
            const int K = DINNER;
            const size_t sAp = (size_t)MROWS*2*K;
            asplit_k<<<(MROWS*K + 255)/256, 256>>>(xcf, nullptr, K, K, MROWS, ap);
            asplit_k<<<(MROWS*K + 255)/256, 256>>>(xcb, nullptr, K, K, MROWS, ap + sAp);
            bsplit_k<<<(64*K + 255)/256, 256>>>(xproj_w  + (size_t)l*K*64, K, 64, bp);
            bsplit_k<<<(64*K + 255)/256, 256>>>(xproj_wb + (size_t)l*K*64, K, 64,
                                                bp + (size_t)64*2*K);
            cudaMemsetAsync(prj, 0, (size_t)2*MROWS*64*sizeof(float), 0);
            launch_mg<128,64,EPI_NONE,true>(ap, sAp, bp, (size_t)64*2*K,
                                            nullptr, nullptr,
                                            prj, 64, (size_t)MROWS*64, 2, 4, K);
        }

        // ---- dt = softplus(prj[:, :32] @ dt_w[32x1024] + bias), batched
        {
            const int K = DTRANK;   // 32
            const size_t sAp = (size_t)MROWS*2*K;
            asplit_k<<<(MROWS*K + 255)/256, 256>>>(prjf, nullptr, 64, K, MROWS, ap);
            asplit_k<<<(MROWS*K + 255)/256, 256>>>(prjb, nullptr, 64, K, MROWS, ap + sAp);
            bsplit_k<<<(DINNER*K + 255)/256, 256>>>(dt_w  + (size_t)l*K*DINNER,
                                                    K, DINNER, bp);
            bsplit_k<<<(DINNER*K + 255)/256, 256>>>(dt_wb + (size_t)l*K*DINNER,
                                                    K, DINNER, bp + (size_t)DINNER*2*K);
            launch_mg<128,128,EPI_SOFTPLUS,false>(ap, sAp, bp, (size_t)DINNER*2*K,
                                                  dt_bias  + (size_t)l*DINNER,
                                                  dt_biasb + (size_t)l*DINNER,
                                                  dtv, DINNER, (size_t)MROWS*DINNER, 2, 1, K);
        }

        scan_k<<<dim3(DINNER/128, BATCH, 2), 128>>>(
            dtf, dtb, xcf, xcb, prjf, prjb,
            A_log  + (size_t)l*DINNER*DSTATE, A_logb + (size_t)l*DINNER*DSTATE,
            D_skip + (size_t)l*DINNER,        D_skipb + (size_t)l*DINNER,
            xz, yf, yb);

        // ---- out_proj on (yf + yb)
        {
            const int K = DINNER;
            asplit_k<<<(MROWS*K + 255)/256, 256>>>(yf, yb, K, K, MROWS, ap);
            bsplit_k<<<(DMODEL*K + 255)/256, 256>>>(out_proj + (size_t)l*K*DMODEL,
                                                    K, DMODEL, bp);
            launch_mg<128,64,EPI_NONE,false>(ap, 0, bp, 0, nullptr, nullptr,
                                             t512, DMODEL, 0, 1, 1, K);
        }

        ln_res_k<<<MROWS, 256>>>(t512, ln1_g + (size_t)l*DMODEL,
                                 ln1_b + (size_t)l*DMODEL, xt, nullptr);

        // ---- fc1
        {
            const int K = DMODEL;
            asplit_k<<<(MROWS*K + 255)/256, 256>>>(xt, nullptr, K, K, MROWS, ap);
            bsplit_k<<<(1024*K + 255)/256, 256>>>(fc1_w + (size_t)l*K*1024,
                                                  K, 1024, bp);
            launch_mg<128,128,EPI_GELU,false>(ap, 0, bp, 0,
                                              fc1_b + (size_t)l*1024, nullptr,
                                              mid, 1024, 0, 1, 1, K);
        }
        // ---- fc2
        {
            const int K = 1024;
            asplit_k<<<(MROWS*K + 255)/256, 256>>>(mid, nullptr, K, K, MROWS, ap);
            bsplit_k<<<(DMODEL*K + 255)/256, 256>>>(fc2_w + (size_t)l*K*DMODEL,
                                                    K, DMODEL, bp);
            launch_mg<128,64,EPI_BIAS,false>(ap, 0, bp, 0,
                                             fc2_b + (size_t)l*DMODEL, nullptr,
                                             t512, DMODEL, 0, 1, 1, K);
        }

        ln_res_k<<<MROWS, 256>>>(t512, ln2_g + (size_t)l*DMODEL,
                                 ln2_b + (size_t)l*DMODEL, xt,
                                 out + (size_t)l*MROWS*DMODEL);
    }
}

// round 17
// speedup vs baseline: 1.9166x; 1.0772x over previous
#include <cuda_runtime.h>
#include <cuda_bf16.h>
#include <math.h>
#include <stdint.h>

#define NLAYER 8
#define DMODEL 512
#define DINNER 1024
#define DSTATE 16
#define DCONV  4
#define DTRANK 32
#define BATCH  8
#define SEQ    800
#define MROWS  (BATCH*SEQ)   // 6400

// ---------------- scratch (static device globals) ------------------------------
__device__ float g_pin [MROWS*1024];
__device__ float g_xt  [MROWS*DMODEL];
__device__ float g_xz  [MROWS*2*DINNER];
__device__ float g_xc  [2*MROWS*DINNER];   // fwd | bwd conv outputs
__device__ float g_prj [2*MROWS*64];       // fwd | bwd xproj outputs
__device__ float g_dt  [2*MROWS*DINNER];   // fwd | bwd dt
__device__ float g_yf  [MROWS*DINNER];
__device__ float g_yb  [MROWS*DINNER];
__device__ float g_t512[MROWS*DMODEL];
__device__ float g_mid [MROWS*DINNER];
// bf16 split operands [hi|lo] (16B aligned for cp.async), 2 batches
__device__ __align__(16) __nv_bfloat16 g_ap[(size_t)2*MROWS*2048];
__device__ __align__(16) __nv_bfloat16 g_bp[(size_t)2*2048*2048];

#define EPI_NONE     0
#define EPI_BIAS     1
#define EPI_SOFTPLUS 2
#define EPI_GELU     3

__device__ __forceinline__ float silu_f(float x) {
    return x * (1.0f / (1.0f + __expf(-x)));
}

__device__ __forceinline__ uint32_t smem_u32(const void* p) {
    uint32_t a;
    asm("{ .reg .u64 t; cvta.to.shared.u64 t, %1; cvt.u32.u64 %0, t; }"
        : "=r"(a) : "l"(p));
    return a;
}

// ---------------- baseline-PTX async copy + ldmatrix + mma ---------------------
#define CP_ASYNC16(dst, src) \
    asm volatile("cp.async.cg.shared.global [%0], [%1], 16;" \
                 :: "r"(dst), "l"(src))
#define CP_COMMIT() asm volatile("cp.async.commit_group;" ::: "memory")
#define CP_WAIT(n)  asm volatile("cp.async.wait_group %0;" :: "n"(n) : "memory")

#define LDMATRIX_X4(r0, r1, r2, r3, addr) \
    asm volatile("ldmatrix.sync.aligned.m8n8.x4.shared.b16 {%0,%1,%2,%3}, [%4];" \
                 : "=r"(r0), "=r"(r1), "=r"(r2), "=r"(r3) : "r"(addr))

#define MMA16816(c, a, b0v, b1v) \
    asm volatile("mma.sync.aligned.m16n8k16.row.col.f32.bf16.bf16.f32 " \
                 "{%0,%1,%2,%3}, {%4,%5,%6,%7}, {%8,%9}, {%0,%1,%2,%3};" \
                 : "+f"((c)[0]), "+f"((c)[1]), "+f"((c)[2]), "+f"((c)[3]) \
                 : "r"((a)[0]), "r"((a)[1]), "r"((a)[2]), "r"((a)[3]), \
                   "r"(b0v), "r"(b1v))

// ---------------- split-precision conversion kernels ---------------------------
// A' = [hi | lo] over K (2K cols), A2 optionally added first.
__global__ void asplit_k(const float* __restrict__ A, const float* __restrict__ A2,
                         int lda, int K, int M, __nv_bfloat16* __restrict__ Ap)
{
    int idx = blockIdx.x * 256 + threadIdx.x;
    if (idx >= M * K) return;
    int k = idx % K, r = idx / K;
    float v = A[(size_t)r*lda + k];
    if (A2) v += A2[(size_t)r*lda + k];
    __nv_bfloat16 hi = __float2bfloat16(v);
    __nv_bfloat16 lo = __float2bfloat16(v - __bfloat162float(hi));
    __nv_bfloat16* row = Ap + (size_t)r*(2*K);
    row[k]     = hi;
    row[K + k] = lo;
}

// B' (transposed): W[K x N] -> Bp[N x 2K] as [hi | lo]
__global__ void bsplit_k(const float* __restrict__ W, int K, int N,
                         __nv_bfloat16* __restrict__ Bp)
{
    int idx = blockIdx.x * 256 + threadIdx.x;
    if (idx >= N * K) return;
    int k = idx % K, n = idx / K;
    float v = W[(size_t)k*N + n];
    __nv_bfloat16 hi = __float2bfloat16(v);
    __nv_bfloat16 lo = __float2bfloat16(v - __bfloat162float(hi));
    __nv_bfloat16* row = Bp + (size_t)n*(2*K);
    row[k]     = hi;
    row[K + k] = lo;
}

// ---------------- bf16 mma.sync GEMM (fused 3-pass per chunk, S=2) -------------
// C[M,N] (fp32) = A @ B^T as Ahi*Bhi + Ahi*Blo + Alo*Bhi. Compact [hi|lo]
// operands (row stride 2K). Per 32-K chunk: stage Ahi|Alo|Bhi|Blo once, run all
// three passes with fragment reuse. 256 threads = 8 warps (2 M x 4 N).
// blockIdx.z encodes (batch, kslice). ATOMIC: atomicAdd into pre-zeroed C.
template<int BM, int BN, int EPI, bool ATOMIC>
__global__ __launch_bounds__(256)
void mgemm_k(const __nv_bfloat16* __restrict__ Ap, size_t strA,
             const __nv_bfloat16* __restrict__ Bp, size_t strB,
             const float* __restrict__ bias0, const float* __restrict__ bias1,
             float* __restrict__ C, int ldc, size_t strC,
             int Kd, int splitK)
{
    constexpr int MT  = BM/32;            // m16 tiles per warp
    constexpr int NTN = BN/32;            // n8 tiles per warp
    constexpr int NB  = NTN/2;            // b-ldmatrix groups
    constexpr int CH  = 2*(BM + BN)*80;   // bytes per stage (4 half-tiles)
    constexpr int OF_ALO = BM*80;
    constexpr int OF_BHI = 2*BM*80;
    constexpr int OF_BLO = 2*BM*80 + BN*80;

    extern __shared__ char smem[];
    const uint32_t sbase = smem_u32(smem);
    const int tid  = threadIdx.x;
    const int lane = tid & 31, wid = tid >> 5;
    const int wm = wid & 1, wn = wid >> 1;
    const int m0 = blockIdx.y * BM;
    const int n0 = blockIdx.x * BN;
    const int bt = blockIdx.z / splitK;
    const int ksl = blockIdx.z % splitK;

    const int ld = 2*Kd;                 // row stride of compact operands
    const int KC = Kd >> 5;              // 32-wide chunks
    const int CNT = KC / splitK;
    const int beg = ksl * CNT;

    const __nv_bfloat16* Ab = Ap + (size_t)bt*strA;
    const __nv_bfloat16* Bb = Bp + (size_t)bt*strB;
    float* Cb = C + (size_t)bt*strC;
    const float* bias = bt ? bias1 : bias0;

    float acc[MT][NTN][4];
#pragma unroll
    for (int i = 0; i < MT; i++)
#pragma unroll
        for (int j = 0; j < NTN; j++)
#pragma unroll
            for (int q = 0; q < 4; q++) acc[i][j][q] = 0.0f;

    // stage all four half-tiles of chunk kk
    auto stage = [&](int buf, int kk) {
        const uint32_t s0 = sbase + buf*CH;
        const int ko = kk*32;
        const __nv_bfloat16* Ahi = Ab + (size_t)m0*ld + ko;
        const __nv_bfloat16* Alo = Ahi + Kd;
        const __nv_bfloat16* Bhi = Bb + (size_t)n0*ld + ko;
        const __nv_bfloat16* Blo = Bhi + Kd;
#pragma unroll
        for (int i = 0; i < BM/64; i++) {
            int q = tid + i*256;
            int r = q >> 2, sg = q & 3;
            CP_ASYNC16(s0 + r*80 + sg*16,          Ahi + (size_t)r*ld + sg*8);
            CP_ASYNC16(s0 + OF_ALO + r*80 + sg*16, Alo + (size_t)r*ld + sg*8);
        }
#pragma unroll
        for (int i = 0; i < BN/64; i++) {
            int q = tid + i*256;
            int r = q >> 2, sg = q & 3;
            CP_ASYNC16(s0 + OF_BHI + r*80 + sg*16, Bhi + (size_t)r*ld + sg*8);
            CP_ASYNC16(s0 + OF_BLO + r*80 + sg*16, Blo + (size_t)r*ld + sg*8);
        }
    };

    const uint32_t a_rel = (uint32_t)((wm*(BM/2) + (lane & 15)) * 80 + (lane >> 4)*16);
    const uint32_t b_rel = (uint32_t)(
        (wn*(BN/4) + (lane & 7) + ((lane >> 4) << 3)) * 80 + (((lane >> 3) & 1)*16));

    auto compute = [&](int buf) {
        const uint32_t s0 = sbase + buf*CH;
#pragma unroll
        for (int ks = 0; ks < 2; ks++) {
            uint32_t af[MT][4];           // Ahi, later reused for Alo
            uint32_t bh[NB][4], bl[NB][4];
#pragma unroll
            for (int mt = 0; mt < MT; mt++)
                LDMATRIX_X4(af[mt][0], af[mt][1], af[mt][2], af[mt][3],
                            s0 + a_rel + (uint32_t)(mt*16*80 + ks*32));
#pragma unroll
            for (int nb = 0; nb < NB; nb++) {
                LDMATRIX_X4(bh[nb][0], bh[nb][1], bh[nb][2], bh[nb][3],
                            s0 + OF_BHI + b_rel + (uint32_t)(nb*16*80 + ks*32));
                LDMATRIX_X4(bl[nb][0], bl[nb][1], bl[nb][2], bl[nb][3],
                            s0 + OF_BLO + b_rel + (uint32_t)(nb*16*80 + ks*32));
            }
            // pass0: Ahi*Bhi   pass1: Ahi*Blo
#pragma unroll
            for (int nb = 0; nb < NB; nb++)
#pragma unroll
                for (int mt = 0; mt < MT; mt++) {
                    MMA16816(acc[mt][2*nb+0], af[mt], bh[nb][0], bh[nb][1]);
                    MMA16816(acc[mt][2*nb+1], af[mt], bh[nb][2], bh[nb][3]);
                    MMA16816(acc[mt][2*nb+0], af[mt], bl[nb][0], bl[nb][1]);
                    MMA16816(acc[mt][2*nb+1], af[mt], bl[nb][2], bl[nb][3]);
                }
            // pass2: Alo*Bhi (reuse af registers)
#pragma unroll
            for (int mt = 0; mt < MT; mt++)
                LDMATRIX_X4(af[mt][0], af[mt][1], af[mt][2], af[mt][3],
                            s0 + OF_ALO + a_rel + (uint32_t)(mt*16*80 + ks*32));
#pragma unroll
            for (int nb = 0; nb < NB; nb++)
#pragma unroll
                for (int mt = 0; mt < MT; mt++) {
                    MMA16816(acc[mt][2*nb+0], af[mt], bh[nb][0], bh[nb][1]);
                    MMA16816(acc[mt][2*nb+1], af[mt], bh[nb][2], bh[nb][3]);
                }
        }
    };

    // 2-stage pipeline, single sync per chunk
    stage(0, beg); CP_COMMIT();
    int buf = 0;
    for (int i = 0; i < CNT; i++) {
        CP_WAIT(0);
        __syncthreads();      // chunk i resident; all warps done compute(i-1)
        if (i + 1 < CNT) { stage(buf ^ 1, beg + i + 1); CP_COMMIT(); }
        compute(buf);
        buf ^= 1;
    }

    // epilogue: fragment c = {C[m][n], C[m][n+1], C[m+8][n], C[m+8][n+1]}
    const int gid = lane >> 2, tig = lane & 3;
#pragma unroll
    for (int mt = 0; mt < MT; mt++) {
#pragma unroll
        for (int nt = 0; nt < NTN; nt++) {
            int m = m0 + wm*(BM/2) + mt*16 + gid;
            int n = n0 + wn*(BN/4) + nt*8 + tig*2;
            float v[4] = {acc[mt][nt][0], acc[mt][nt][1],
                          acc[mt][nt][2], acc[mt][nt][3]};
            if (!ATOMIC) {
#pragma unroll
                for (int q = 0; q < 4; q++) {
                    float w = v[q];
                    if (EPI == EPI_BIAS || EPI == EPI_SOFTPLUS || EPI == EPI_GELU)
                        w += bias[n + (q & 1)];
                    if (EPI == EPI_SOFTPLUS)
                        w = (w > 0.0f) ? (w + log1pf(__expf(-w))) : log1pf(__expf(w));
                    if (EPI == EPI_GELU)
                        w = 0.5f * w * (1.0f + erff(w * 0.70710678118654752f));
                    v[q] = w;
                }
                *reinterpret_cast<float2*>(Cb + (size_t)m*ldc + n)     = make_float2(v[0], v[1]);
                *reinterpret_cast<float2*>(Cb + (size_t)(m+8)*ldc + n) = make_float2(v[2], v[3]);
            } else {
                atomicAdd(Cb + (size_t)m*ldc + n,       v[0]);
                atomicAdd(Cb + (size_t)m*ldc + n + 1,   v[1]);
                atomicAdd(Cb + (size_t)(m+8)*ldc + n,   v[2]);
                atomicAdd(Cb + (size_t)(m+8)*ldc + n+1, v[3]);
            }
        }
    }
}

template<int BM, int BN, int EPI, bool ATOMIC>
static void launch_mg(const __nv_bfloat16* ap, size_t strA,
                      const __nv_bfloat16* bp, size_t strB,
                      const float* b0, const float* b1,
                      float* C, int N, size_t strC,
                      int batch, int splitK, int Kd)
{
    const int smem = 2*2*(BM+BN)*80;
    cudaFuncSetAttribute(mgemm_k<BM,BN,EPI,ATOMIC>,
                         cudaFuncAttributeMaxDynamicSharedMemorySize, smem);
    dim3 grid(N/BN, MROWS/BM, batch*splitK);
    mgemm_k<BM,BN,EPI,ATOMIC><<<grid, 256, smem>>>(
        ap, strA, bp, strB, b0, b1, C, N, strC, Kd, splitK);
}

// ---------------- patch gather -------------------------------------------------
__global__ void gather_k(const float* __restrict__ x, float* __restrict__ pin)
{
    int idx = blockIdx.x * blockDim.x + threadIdx.x;
    if (idx >= MROWS*1024) return;
    int k   = idx & 1023;
    int row = idx >> 10;
    int b = row / SEQ, t = row % SEQ;
    int f = t / 100, rem = t % 100;
    int hh = rem / 10, ww = rem % 10;
    int p1 = k >> 6;
    int r2 = k & 63;
    int p2 = r2 >> 2;
    int pf = r2 & 3;
    size_t src = (((size_t)b*32 + (f*4 + pf))*160 + (hh*16 + p1))*160 + (ww*16 + p2);
    pin[idx] = x[src];
}

// ---------------- depthwise causal conv (fwd + reversed) + SiLU ----------------
__global__ void conv_k(const float* __restrict__ xz,
                       const float* __restrict__ wf, const float* __restrict__ bf,
                       const float* __restrict__ wb, const float* __restrict__ bb,
                       float* __restrict__ xcf, float* __restrict__ xcb)
{
    int idx = blockIdx.x * blockDim.x + threadIdx.x;
    if (idx >= MROWS*DINNER) return;
    int d   = idx & (DINNER-1);
    int row = idx >> 10;
    int b = row / SEQ, t = row % SEQ;
    const float* base = xz + (size_t)b*SEQ*2048 + d;

    float w0 = wf[d*4+0], w1 = wf[d*4+1], w2 = wf[d*4+2], w3 = wf[d*4+3];
    float acc = bf[d];
    acc = fmaf(w3, base[(size_t)t*2048], acc);
    if (t >= 1) acc = fmaf(w2, base[(size_t)(t-1)*2048], acc);
    if (t >= 2) acc = fmaf(w1, base[(size_t)(t-2)*2048], acc);
    if (t >= 3) acc = fmaf(w0, base[(size_t)(t-3)*2048], acc);
    xcf[(size_t)row*DINNER + d] = silu_f(acc);

    float v0 = wb[d*4+0], v1 = wb[d*4+1], v2 = wb[d*4+2], v3 = wb[d*4+3];
    float accb = bb[d];
    accb = fmaf(v3, base[(size_t)(SEQ-1-t)*2048], accb);
    if (t >= 1) accb = fmaf(v2, base[(size_t)(SEQ-t)*2048], accb);
    if (t >= 2) accb = fmaf(v1, base[(size_t)(SEQ+1-t)*2048], accb);
    if (t >= 3) accb = fmaf(v0, base[(size_t)(SEQ+2-t)*2048], accb);
    xcb[(size_t)row*DINNER + d] = silu_f(accb);
}

// ---------------- selective-scan (both directions) -----------------------------
__global__ __launch_bounds__(128)
void scan_k(const float* __restrict__ dtf, const float* __restrict__ dtb,
            const float* __restrict__ uf,  const float* __restrict__ ub,
            const float* __restrict__ pf,  const float* __restrict__ pb,
            const float* __restrict__ Af,  const float* __restrict__ Ab,
            const float* __restrict__ Df,  const float* __restrict__ Db,
            const float* __restrict__ xz,
            float* __restrict__ yf, float* __restrict__ yb)
{
    const int d   = blockIdx.x * 128 + threadIdx.x;
    const int b   = blockIdx.y;
    const int dir = blockIdx.z;

    const float* dtp = dir ? dtb : dtf;
    const float* up  = dir ? ub  : uf;
    const float* pp  = dir ? pb  : pf;
    const float* Ap  = dir ? Ab  : Af;
    const float* Dp  = dir ? Db  : Df;
    float*       yp  = dir ? yb  : yf;

    float A[DSTATE];
#pragma unroll
    for (int n = 0; n < DSTATE; n++) A[n] = -expf(Ap[(size_t)d*DSTATE + n]);
    const float Dv = Dp[d];

    bool fast = true;
#pragma unroll
    for (int n = 1; n < DSTATE; n++) {
        float ex = A[0] * (float)(n+1);
        fast = fast && (fabsf(A[n] - ex) <= 1e-4f * fabsf(ex) + 1e-6f);
    }

    float h[DSTATE];
#pragma unroll
    for (int n = 0; n < DSTATE; n++) h[n] = 0.0f;

    int row = b*SEQ;
    float dt_c = dtp[(size_t)row*DINNER + d];
    float u_c  = up [(size_t)row*DINNER + d];
    const float4* bc = reinterpret_cast<const float4*>(pp + (size_t)row*64 + 32);
    float4 Bq[4] = {bc[0], bc[1], bc[2], bc[3]};
    float4 Cq[4] = {bc[4], bc[5], bc[6], bc[7]};
    int orow0 = dir ? (b*SEQ + SEQ-1) : row;
    float z_c = xz[(size_t)orow0*2048 + DINNER + d];

    for (int t = 0; t < SEQ; t++) {
        const float dt = dt_c, u = u_c, zv = z_c;
        float Bv[16] = {Bq[0].x,Bq[0].y,Bq[0].z,Bq[0].w, Bq[1].x,Bq[1].y,Bq[1].z,Bq[1].w,
                        Bq[2].x,Bq[2].y,Bq[2].z,Bq[2].w, Bq[3].x,Bq[3].y,Bq[3].z,Bq[3].w};
        float Cv[16] = {Cq[0].x,Cq[0].y,Cq[0].z,Cq[0].w, Cq[1].x,Cq[1].y,Cq[1].z,Cq[1].w,
                        Cq[2].x,Cq[2].y,Cq[2].z,Cq[2].w, Cq[3].x,Cq[3].y,Cq[3].z,Cq[3].w};
        const int orow = dir ? (b*SEQ + (SEQ-1-t)) : (b*SEQ + t);

        if (t + 1 < SEQ) {
            const int nrow = b*SEQ + t + 1;
            dt_c = dtp[(size_t)nrow*DINNER + d];
            u_c  = up [(size_t)nrow*DINNER + d];
            const float4* nbc = reinterpret_cast<const float4*>(pp + (size_t)nrow*64 + 32);
            Bq[0]=nbc[0]; Bq[1]=nbc[1]; Bq[2]=nbc[2]; Bq[3]=nbc[3];
            Cq[0]=nbc[4]; Cq[1]=nbc[5]; Cq[2]=nbc[6]; Cq[3]=nbc[7];
            const int norow = dir ? (b*SEQ + (SEQ-2-t)) : nrow;
            z_c = xz[(size_t)norow*2048 + DINNER + d];
        }

        float e[16];
        if (fast) {
            float r  = __expf(dt * A[0]);
            float r2 = r*r, r4 = r2*r2, r8 = r4*r4;
            e[0]=r;       e[1]=r2;      e[2]=r2*r;     e[3]=r4;
            e[4]=r4*r;    e[5]=r4*r2;   e[6]=r4*e[2];  e[7]=r8;
            e[8]=r8*r;    e[9]=r8*r2;   e[10]=r8*e[2]; e[11]=r8*r4;
            e[12]=r8*e[4];e[13]=r8*e[5];e[14]=r8*e[6]; e[15]=r8*r8;
        } else {
#pragma unroll
            for (int n = 0; n < 16; n++) e[n] = __expf(dt * A[n]);
        }

        const float du = dt * u;
        float a0=0.f, a1=0.f, a2=0.f, a3=0.f;
#pragma unroll
        for (int n = 0; n < 16; n += 4) {
            h[n+0] = fmaf(e[n+0], h[n+0], du * Bv[n+0]);
            h[n+1] = fmaf(e[n+1], h[n+1], du * Bv[n+1]);
            h[n+2] = fmaf(e[n+2], h[n+2], du * Bv[n+2]);
            h[n+3] = fmaf(e[n+3], h[n+3], du * Bv[n+3]);
            a0 = fmaf(h[n+0], Cv[n+0], a0);
            a1 = fmaf(h[n+1], Cv[n+1], a1);
            a2 = fmaf(h[n+2], Cv[n+2], a2);
            a3 = fmaf(h[n+3], Cv[n+3], a3);
        }
        float y = (a0+a1) + (a2+a3) + u * Dv;
        yp[(size_t)orow*DINNER + d] = y * silu_f(zv);
    }
}

// ---------------- LayerNorm + residual -----------------------------------------
__global__ __launch_bounds__(256)
void ln_res_k(const float* __restrict__ y, const float* __restrict__ g,
              const float* __restrict__ be, float* __restrict__ xt,
              float* __restrict__ outp)
{
    const int row = blockIdx.x;
    const int tid = threadIdx.x;
    const float v0 = y[(size_t)row*DMODEL + tid];
    const float v1 = y[(size_t)row*DMODEL + 256 + tid];
    float s  = v0 + v1;
    float ss = v0*v0 + v1*v1;
#pragma unroll
    for (int off = 16; off > 0; off >>= 1) {
        s  += __shfl_xor_sync(0xffffffffu, s,  off);
        ss += __shfl_xor_sync(0xffffffffu, ss, off);
    }
    __shared__ float sh[2][8];
    const int wid = tid >> 5, lane = tid & 31;
    if (lane == 0) { sh[0][wid] = s; sh[1][wid] = ss; }
    __syncthreads();
    float ts = 0.f, tss = 0.f;
#pragma unroll
    for (int i = 0; i < 8; i++) { ts += sh[0][i]; tss += sh[1][i]; }
    const float mean = ts * (1.0f/DMODEL);
    const float var  = tss * (1.0f/DMODEL) - mean*mean;
    const float rstd = rsqrtf(var + 1e-5f);

    float o0 = (v0 - mean)*rstd*g[tid]     + be[tid]     + xt[(size_t)row*DMODEL + tid];
    float o1 = (v1 - mean)*rstd*g[256+tid] + be[256+tid] + xt[(size_t)row*DMODEL + 256 + tid];
    xt[(size_t)row*DMODEL + tid]       = o0;
    xt[(size_t)row*DMODEL + 256 + tid] = o1;
    if (outp) {
        outp[(size_t)row*DMODEL + tid]       = o0;
        outp[(size_t)row*DMODEL + 256 + tid] = o1;
    }
}

// ---------------- host orchestration -------------------------------------------
extern "C" void kernel_launch(void* const* d_in, const int* in_sizes, int n_in,
                              void* d_out, int out_size)
{
    (void)in_sizes; (void)n_in; (void)out_size;
    const float* x        = (const float*)d_in[0];
    const float* patch_w  = (const float*)d_in[1];
    const float* patch_b  = (const float*)d_in[2];
    const float* in_proj  = (const float*)d_in[3];
    const float* conv_w   = (const float*)d_in[4];
    const float* conv_b   = (const float*)d_in[5];
    const float* xproj_w  = (const float*)d_in[6];
    const float* dt_w     = (const float*)d_in[7];
    const float* dt_bias  = (const float*)d_in[8];
    const float* A_log    = (const float*)d_in[9];
    const float* D_skip   = (const float*)d_in[10];
    const float* conv_wb  = (const float*)d_in[11];
    const float* conv_bb  = (const float*)d_in[12];
    const float* xproj_wb = (const float*)d_in[13];
    const float* dt_wb    = (const float*)d_in[14];
    const float* dt_biasb = (const float*)d_in[15];
    const float* A_logb   = (const float*)d_in[16];
    const float* D_skipb  = (const float*)d_in[17];
    const float* out_proj = (const float*)d_in[18];
    const float* ln1_g    = (const float*)d_in[19];
    const float* ln1_b    = (const float*)d_in[20];
    const float* fc1_w    = (const float*)d_in[21];
    const float* fc1_b    = (const float*)d_in[22];
    const float* fc2_w    = (const float*)d_in[23];
    const float* fc2_b    = (const float*)d_in[24];
    const float* ln2_g    = (const float*)d_in[25];
    const float* ln2_b    = (const float*)d_in[26];
    float* out = (float*)d_out;

    float *pin, *xt, *xz, *xc, *prj, *dtv, *yf, *yb, *t512, *mid;
    __nv_bfloat16 *ap, *bp;
    cudaGetSymbolAddress((void**)&pin,  g_pin);
    cudaGetSymbolAddress((void**)&xt,   g_xt);
    cudaGetSymbolAddress((void**)&xz,   g_xz);
    cudaGetSymbolAddress((void**)&xc,   g_xc);
    cudaGetSymbolAddress((void**)&prj,  g_prj);
    cudaGetSymbolAddress((void**)&dtv,  g_dt);
    cudaGetSymbolAddress((void**)&yf,   g_yf);
    cudaGetSymbolAddress((void**)&yb,   g_yb);
    cudaGetSymbolAddress((void**)&t512, g_t512);
    cudaGetSymbolAddress((void**)&mid,  g_mid);
    cudaGetSymbolAddress((void**)&ap,   g_ap);
    cudaGetSymbolAddress((void**)&bp,   g_bp);

    float* xcf = xc;
    float* xcb = xc + (size_t)MROWS*DINNER;
    float* prjf = prj;
    float* prjb = prj + (size_t)MROWS*64;
    float* dtf = dtv;
    float* dtb = dtv + (size_t)MROWS*DINNER;

    // ---- patch embed: pin[6400x1024] @ patch_w[1024x512] + b
    gather_k<<<(MROWS*1024 + 255)/256, 256>>>(x, pin);
    {
        const int K = 1024;
        asplit_k<<<(MROWS*K + 255)/256, 256>>>(pin, nullptr, K, K, MROWS, ap);
        bsplit_k<<<(512*K + 255)/256, 256>>>(patch_w, K, 512, bp);
        launch_mg<128,64,EPI_BIAS,false>(ap, 0, bp, 0, patch_b, nullptr,
                                         xt, 512, 0, 1, 1, K);
    }

    for (int l = 0; l < NLAYER; l++) {
        // ---- in_proj: xz = xt @ W[512x2048]
        {
            const int K = 512;
            asplit_k<<<(MROWS*K + 255)/256, 256>>>(xt, nullptr, K, K, MROWS, ap);
            bsplit_k<<<(2048*K + 255)/256, 256>>>(in_proj + (size_t)l*512*2048,
                                                  K, 2048, bp);
            launch_mg<128,128,EPI_NONE,false>(ap, 0, bp, 0, nullptr, nullptr,
                                              xz, 2048, 0, 1, 1, K);
        }

        conv_k<<<(MROWS*DINNER + 255)/256, 256>>>(
            xz,
            conv_w  + (size_t)l*DINNER*DCONV, conv_b  + (size_t)l*DINNER,
            conv_wb + (size_t)l*DINNER*DCONV, conv_bb + (size_t)l*DINNER,
            xcf, xcb);

        // ---- x-proj (N=64), batched fwd+bwd, split-K x4, atomic into zeroed prj
        {
            const int K = DINNER;
            const size_t sAp = (size_t)MROWS*2*K;
            asplit_k<<<(MROWS*K + 255)/256, 256>>>(xcf, nullptr, K, K, MROWS, ap);
            asplit_k<<<(MROWS*K + 255)/256, 256>>>(xcb, nullptr, K, K, MROWS, ap + sAp);
            bsplit_k<<<(64*K + 255)/256, 256>>>(xproj_w  + (size_t)l*K*64, K, 64, bp);
            bsplit_k<<<(64*K + 255)/256, 256>>>(xproj_wb + (size_t)l*K*64, K, 64,
                                                bp + (size_t)64*2*K);
            cudaMemsetAsync(prj, 0, (size_t)2*MROWS*64*sizeof(float), 0);
            launch_mg<128,64,EPI_NONE,true>(ap, sAp, bp, (size_t)64*2*K,
                                            nullptr, nullptr,
                                            prj, 64, (size_t)MROWS*64, 2, 4, K);
        }

        // ---- dt = softplus(prj[:, :32] @ dt_w[32x1024] + bias), batched
        {
            const int K = DTRANK;   // 32
            const size_t sAp = (size_t)MROWS*2*K;
            asplit_k<<<(MROWS*K + 255)/256, 256>>>(prjf, nullptr, 64, K, MROWS, ap);
            asplit_k<<<(MROWS*K + 255)/256, 256>>>(prjb, nullptr, 64, K, MROWS, ap + sAp);
            bsplit_k<<<(DINNER*K + 255)/256, 256>>>(dt_w  + (size_t)l*K*DINNER,
                                                    K, DINNER, bp);
            bsplit_k<<<(DINNER*K + 255)/256, 256>>>(dt_wb + (size_t)l*K*DINNER,
                                                    K, DINNER, bp + (size_t)DINNER*2*K);
            launch_mg<128,128,EPI_SOFTPLUS,false>(ap, sAp, bp, (size_t)DINNER*2*K,
                                                  dt_bias  + (size_t)l*DINNER,
                                                  dt_biasb + (size_t)l*DINNER,
                                                  dtv, DINNER, (size_t)MROWS*DINNER, 2, 1, K);
        }

        scan_k<<<dim3(DINNER/128, BATCH, 2), 128>>>(
            dtf, dtb, xcf, xcb, prjf, prjb,
            A_log  + (size_t)l*DINNER*DSTATE, A_logb + (size_t)l*DINNER*DSTATE,
            D_skip + (size_t)l*DINNER,        D_skipb + (size_t)l*DINNER,
            xz, yf, yb);

        // ---- out_proj on (yf + yb)
        {
            const int K = DINNER;
            asplit_k<<<(MROWS*K + 255)/256, 256>>>(yf, yb, K, K, MROWS, ap);
            bsplit_k<<<(DMODEL*K + 255)/256, 256>>>(out_proj + (size_t)l*K*DMODEL,
                                                    K, DMODEL, bp);
            launch_mg<128,64,EPI_NONE,false>(ap, 0, bp, 0, nullptr, nullptr,
                                             t512, DMODEL, 0, 1, 1, K);
        }

        ln_res_k<<<MROWS, 256>>>(t512, ln1_g + (size_t)l*DMODEL,
                                 ln1_b + (size_t)l*DMODEL, xt, nullptr);

        // ---- fc1
        {
            const int K = DMODEL;
            asplit_k<<<(MROWS*K + 255)/256, 256>>>(xt, nullptr, K, K, MROWS, ap);
            bsplit_k<<<(1024*K + 255)/256, 256>>>(fc1_w + (size_t)l*K*1024,
                                                  K, 1024, bp);
            launch_mg<128,128,EPI_GELU,false>(ap, 0, bp, 0,
                                              fc1_b + (size_t)l*1024, nullptr,
                                              mid, 1024, 0, 1, 1, K);
        }
        // ---- fc2
        {
            const int K = 1024;
            asplit_k<<<(MROWS*K + 255)/256, 256>>>(mid, nullptr, K, K, MROWS, ap);
            bsplit_k<<<(DMODEL*K + 255)/256, 256>>>(fc2_w + (size_t)l*K*DMODEL,
                                                    K, DMODEL, bp);
            launch_mg<128,64,EPI_BIAS,false>(ap, 0, bp, 0,
                                             fc2_b + (size_t)l*DMODEL, nullptr,
                                             t512, DMODEL, 0, 1, 1, K);
        }

        ln_res_k<<<MROWS, 256>>>(t512, ln2_g + (size_t)l*DMODEL,
                                 ln2_b + (size_t)l*DMODEL, xt,
                                 out + (size_t)l*MROWS*DMODEL);
    }
}